// round 1
// baseline (speedup 1.0000x reference)
#include <cuda_runtime.h>

// Problem-shape constants (from reference setup_inputs)
#define MAXN 100000
#define MAXE 1600000
#define FIN 128
#define HH 64   // half hidden

// ---------------- device scratch (no allocations allowed) ----------------
__device__ int    g_is64;
__device__ int    g_deg[MAXN];
__device__ float  g_dinv[MAXN];
__device__ float4 g_xs [MAXN * 16];   // dinv[n] * (x@W1)[n]  (64 floats/node)
__device__ float4 g_xf [MAXN * 16];   // (x@Wf1)[n] + bf1     (64 floats/node)
__device__ float4 g_agg[MAXN * 16];   // GCN1 accumulator     (64 floats/node)
__device__ float  g_u  [MAXN];        // dinv[n] * (h[n]@W2)

// ---------------- edge-index dtype detection ----------------
// jnp arrays may come through as int32 (x64 disabled) or int64. If the data is
// int32, interpreting 8-byte words as int64 yields values >= 2^32 almost surely
// (node ids < 1e5). If truly int64, every word < 1e5.
__global__ void detect_kernel(const unsigned long long* __restrict__ p, int nwords) {
    int bad = 0;
    for (int i = threadIdx.x; i < nwords; i += blockDim.x)
        if (p[i] >= (1ULL << 32)) bad = 1;
    bad = __syncthreads_or(bad);
    if (threadIdx.x == 0) g_is64 = bad ? 0 : 1;
}

__device__ __forceinline__ void load_edge(const void* ei, long long E, long long e,
                                          int& r, int& c) {
    if (g_is64) {
        const long long* p = (const long long*)ei;
        r = (int)p[e]; c = (int)p[E + e];
    } else {
        const int* p = (const int*)ei;
        r = p[e]; c = p[E + e];
    }
}

// ---------------- degree / norm ----------------
__global__ void zero_deg_kernel(int N) {
    int n = blockIdx.x * 256 + threadIdx.x;
    if (n < N) g_deg[n] = 0;
}

__global__ void deg_kernel(const void* __restrict__ ei, long long E) {
    long long e = blockIdx.x * 256LL + threadIdx.x;
    if (e >= E) return;
    int c;
    if (g_is64) c = (int)((const long long*)ei)[E + e];
    else        c = ((const int*)ei)[E + e];
    atomicAdd(&g_deg[c], 1);
}

__global__ void dinv_kernel(int N) {
    int n = blockIdx.x * 256 + threadIdx.x;
    if (n < N) g_dinv[n] = rsqrtf((float)(g_deg[n] + 1));  // +1 self loop
}

// ---------------- layer-1 dual GEMM:  y = x @ [W1 | Wf1]  ----------------
// BM=128 rows/block, 128 output cols, K=128 in 8 chunks of 16, double buffered.
// Epilogue writes xs = dinv*y[:, :64], agg = dinv*xs + b1 (self-loop + bias),
// xf = y[:, 64:] + bf1.
__global__ __launch_bounds__(256, 2) void gemm_kernel(
    const float* __restrict__ x,
    const float* __restrict__ W1, const float* __restrict__ Wf1,
    const float* __restrict__ b1, const float* __restrict__ bf1,
    int N)
{
    __shared__ float As[2][16][132];   // [k][m], padded
    __shared__ float Bs[2][16][128];   // [k][n]

    const int t  = threadIdx.x;
    const int tx = t & 15;       // output col group: cols tx*8 .. tx*8+7
    const int ty = t >> 4;       // output row group: rows ty*8 .. ty*8+7
    const int bm = blockIdx.x * 128;

    float4 aR[2], bR[2];

    auto load_stage = [&](int kc) {
        #pragma unroll
        for (int q = 0; q < 2; q++) {
            int f  = t * 2 + q;
            int m  = f >> 2;            // 0..127 (row within tile)
            int k0 = (f & 3) << 2;      // 0,4,8,12 (k within chunk)
            int gm = bm + m;
            aR[q] = (gm < N) ? *(const float4*)(x + (long long)gm * FIN + kc + k0)
                             : make_float4(0.f, 0.f, 0.f, 0.f);
            int n4 = f & 31;            // float4 col index 0..31
            int kk = f >> 5;            // 0..15
            const float* src = (n4 < 16)
                ? (W1  + (kc + kk) * HH + n4 * 4)
                : (Wf1 + (kc + kk) * HH + (n4 - 16) * 4);
            bR[q] = *(const float4*)src;
        }
    };
    auto store_stage = [&](int bsel) {
        #pragma unroll
        for (int q = 0; q < 2; q++) {
            int f  = t * 2 + q;
            int m  = f >> 2;
            int k0 = (f & 3) << 2;
            As[bsel][k0 + 0][m] = aR[q].x;
            As[bsel][k0 + 1][m] = aR[q].y;
            As[bsel][k0 + 2][m] = aR[q].z;
            As[bsel][k0 + 3][m] = aR[q].w;
            int n4 = f & 31;
            int kk = f >> 5;
            *(float4*)&Bs[bsel][kk][n4 * 4] = bR[q];
        }
    };

    float acc[8][8];
    #pragma unroll
    for (int i = 0; i < 8; i++)
        #pragma unroll
        for (int j = 0; j < 8; j++) acc[i][j] = 0.f;

    load_stage(0);
    store_stage(0);
    __syncthreads();

    int buf = 0;
    #pragma unroll
    for (int s = 0; s < 8; s++) {
        if (s < 7) load_stage((s + 1) * 16);
        #pragma unroll
        for (int kk = 0; kk < 16; kk++) {
            float4 a0  = *(const float4*)&As[buf][kk][ty * 8];
            float4 a1  = *(const float4*)&As[buf][kk][ty * 8 + 4];
            float4 b0  = *(const float4*)&Bs[buf][kk][tx * 8];
            float4 b1v = *(const float4*)&Bs[buf][kk][tx * 8 + 4];
            float av[8] = {a0.x, a0.y, a0.z, a0.w, a1.x, a1.y, a1.z, a1.w};
            float bv[8] = {b0.x, b0.y, b0.z, b0.w, b1v.x, b1v.y, b1v.z, b1v.w};
            #pragma unroll
            for (int i = 0; i < 8; i++)
                #pragma unroll
                for (int j = 0; j < 8; j++)
                    acc[i][j] = fmaf(av[i], bv[j], acc[i][j]);
        }
        if (s < 7) {
            store_stage(buf ^ 1);
            __syncthreads();
            buf ^= 1;
        }
    }

    // epilogue
    #pragma unroll
    for (int i = 0; i < 8; i++) {
        int gm = bm + ty * 8 + i;
        if (gm >= N) continue;
        float dv = g_dinv[gm];
        if (tx < 8) {
            #pragma unroll
            for (int j4 = 0; j4 < 2; j4++) {
                int c0 = tx * 8 + j4 * 4;
                float4 v = make_float4(acc[i][j4 * 4], acc[i][j4 * 4 + 1],
                                       acc[i][j4 * 4 + 2], acc[i][j4 * 4 + 3]);
                float4 xs4 = make_float4(v.x * dv, v.y * dv, v.z * dv, v.w * dv);
                g_xs[(long long)gm * 16 + tx * 2 + j4] = xs4;
                float4 ag = make_float4(xs4.x * dv + b1[c0],
                                        xs4.y * dv + b1[c0 + 1],
                                        xs4.z * dv + b1[c0 + 2],
                                        xs4.w * dv + b1[c0 + 3]);
                g_agg[(long long)gm * 16 + tx * 2 + j4] = ag;
            }
        } else {
            #pragma unroll
            for (int j4 = 0; j4 < 2; j4++) {
                int c0 = (tx - 8) * 8 + j4 * 4;
                float4 v = make_float4(acc[i][j4 * 4]     + bf1[c0],
                                       acc[i][j4 * 4 + 1] + bf1[c0 + 1],
                                       acc[i][j4 * 4 + 2] + bf1[c0 + 2],
                                       acc[i][j4 * 4 + 3] + bf1[c0 + 3]);
                g_xf[(long long)gm * 16 + (tx - 8) * 2 + j4] = v;
            }
        }
    }
}

// ---------------- edge aggregation (layer 1) ----------------
// 16 threads per edge, each moves one float4 (64 floats total).
// agg[c] += dinv[c] * xs[r]   (xs already carries dinv[r])
__global__ void edge_agg_kernel(const void* __restrict__ ei, long long E) {
    long long tid = blockIdx.x * 256LL + threadIdx.x;
    long long e = tid >> 4;
    int l = (int)(tid & 15);
    if (e >= E) return;
    int r, c;
    load_edge(ei, E, e, r, c);
    float sc = g_dinv[c];
    float4 v = g_xs[(long long)r * 16 + l];
    v.x *= sc; v.y *= sc; v.z *= sc; v.w *= sc;
    atomicAdd(&g_agg[(long long)c * 16 + l], v);   // 128-bit RED (sm_90+)
}

// ---------------- finalize: relu + layer-2 dot products ----------------
// One warp per node. h = [relu(agg) ; relu(xf)] (128), s = h@W2, tt = h@Wf2.
// out[n] = dinv^2 * s + b2 + tt + bf2 ;  u[n] = dinv * s.
__global__ void finalize_kernel(const float* __restrict__ W2, const float* __restrict__ b2,
                                const float* __restrict__ Wf2, const float* __restrict__ bf2,
                                float* __restrict__ out, int N)
{
    int gwarp = (blockIdx.x * 256 + threadIdx.x) >> 5;
    int lane  = threadIdx.x & 31;
    if (gwarp >= N) return;
    const float* aggf = (const float*)g_agg + (long long)gwarp * 64;
    const float* xff  = (const float*)g_xf  + (long long)gwarp * 64;
    float a0 = fmaxf(aggf[lane],      0.f);
    float a1 = fmaxf(aggf[lane + 32], 0.f);
    float f0 = fmaxf(xff[lane],       0.f);
    float f1 = fmaxf(xff[lane + 32],  0.f);
    float s  = a0 * W2[lane]  + a1 * W2[lane + 32]  + f0 * W2[lane + 64]  + f1 * W2[lane + 96];
    float tt = a0 * Wf2[lane] + a1 * Wf2[lane + 32] + f0 * Wf2[lane + 64] + f1 * Wf2[lane + 96];
    #pragma unroll
    for (int o = 16; o > 0; o >>= 1) {
        s  += __shfl_xor_sync(0xFFFFFFFFu, s, o);
        tt += __shfl_xor_sync(0xFFFFFFFFu, tt, o);
    }
    if (lane == 0) {
        float dv = g_dinv[gwarp];
        g_u[gwarp] = dv * s;
        out[gwarp] = dv * dv * s + b2[0] + tt + bf2[0];
    }
}

// ---------------- edge aggregation (layer 2, scalar) ----------------
__global__ void edge_out_kernel(const void* __restrict__ ei, long long E,
                                float* __restrict__ out) {
    long long e = blockIdx.x * 256LL + threadIdx.x;
    if (e >= E) return;
    int r, c;
    load_edge(ei, E, e, r, c);
    atomicAdd(&out[c], g_dinv[c] * g_u[r]);
}

// ---------------- launch ----------------
extern "C" void kernel_launch(void* const* d_in, const int* in_sizes, int n_in,
                              void* d_out, int out_size) {
    const float* x   = (const float*)d_in[0];
    const void*  ei  = d_in[1];
    const float* W1  = (const float*)d_in[2];
    const float* b1  = (const float*)d_in[3];
    const float* Wf1 = (const float*)d_in[4];
    const float* bf1 = (const float*)d_in[5];
    const float* W2  = (const float*)d_in[6];
    const float* b2  = (const float*)d_in[7];
    const float* Wf2 = (const float*)d_in[8];
    const float* bf2 = (const float*)d_in[9];
    float* out = (float*)d_out;

    int N = in_sizes[0] / FIN;
    long long E = (long long)in_sizes[1] / 2;

    int nwords = (E < 2048) ? (int)E : 2048;
    detect_kernel<<<1, 256>>>((const unsigned long long*)ei, nwords);
    zero_deg_kernel<<<(N + 255) / 256, 256>>>(N);
    deg_kernel<<<(int)((E + 255) / 256), 256>>>(ei, E);
    dinv_kernel<<<(N + 255) / 256, 256>>>(N);
    gemm_kernel<<<(N + 127) / 128, 256>>>(x, W1, Wf1, b1, bf1, N);
    long long tot = E * 16;
    edge_agg_kernel<<<(int)((tot + 255) / 256), 256>>>(ei, E);
    finalize_kernel<<<(int)(((long long)N * 32 + 255) / 256), 256>>>(W2, b2, Wf2, bf2, out, N);
    edge_out_kernel<<<(int)((E + 255) / 256), 256>>>(ei, E, out);
}

// round 2
// speedup vs baseline: 1.1894x; 1.1894x over previous
#include <cuda_runtime.h>

#define MAXN 100000
#define MAXE 1600000
#define FIN 128
#define HH 64
#define NB_MAX 512          // max scan blocks (ceil(100000/256)=391)

// ---------------- device scratch ----------------
__device__ int    g_is64;
__device__ int    g_deg[MAXN];
__device__ int    g_rowstart[MAXN];
__device__ int    g_cursor[MAXN];
__device__ int    g_src[MAXE];
__device__ int    g_part[NB_MAX];
__device__ int    g_poff[NB_MAX];
__device__ float  g_dinv[MAXN];
__device__ float4 g_xs[MAXN * 16];   // dinv[n] * (x@W1)[n]
__device__ float4 g_xf[MAXN * 16];   // (x@Wf1)[n] + bf1
__device__ float  g_u [MAXN];        // dinv[n] * (h[n]@W2)

// ---------------- edge dtype detection ----------------
__global__ void detect_kernel(const unsigned long long* __restrict__ p, int nwords) {
    int bad = 0;
    for (int i = threadIdx.x; i < nwords; i += blockDim.x)
        if (p[i] >= (1ULL << 32)) bad = 1;
    bad = __syncthreads_or(bad);
    if (threadIdx.x == 0) g_is64 = bad ? 0 : 1;
}

__device__ __forceinline__ void load_edge(const void* ei, long long E, long long e,
                                          int& r, int& c) {
    if (g_is64) {
        const long long* p = (const long long*)ei;
        r = (int)p[e]; c = (int)p[E + e];
    } else {
        const int* p = (const int*)ei;
        r = p[e]; c = p[E + e];
    }
}

// ---------------- degree / CSR build ----------------
__global__ void zero_deg_kernel(int N) {
    int n = blockIdx.x * 256 + threadIdx.x;
    if (n < N) g_deg[n] = 0;
}

__global__ void count_kernel(const void* __restrict__ ei, long long E) {
    long long e = blockIdx.x * 256LL + threadIdx.x;
    if (e >= E) return;
    int c;
    if (g_is64) c = (int)((const long long*)ei)[E + e];
    else        c = ((const int*)ei)[E + e];
    atomicAdd(&g_deg[c], 1);
}

// per-block sums of deg
__global__ void scanA_kernel(int N) {
    __shared__ int s[8];
    int n = blockIdx.x * 256 + threadIdx.x;
    int v = (n < N) ? g_deg[n] : 0;
    #pragma unroll
    for (int o = 16; o > 0; o >>= 1) v += __shfl_xor_sync(0xFFFFFFFFu, v, o);
    if ((threadIdx.x & 31) == 0) s[threadIdx.x >> 5] = v;
    __syncthreads();
    if (threadIdx.x == 0) {
        int t = 0;
        #pragma unroll
        for (int i = 0; i < 8; i++) t += s[i];
        g_part[blockIdx.x] = t;
    }
}

// single-block exclusive scan over block partials
__global__ void scanB_kernel(int nb) {
    __shared__ int s[NB_MAX];
    int t = threadIdx.x;
    int v = (t < nb) ? g_part[t] : 0;
    s[t] = v;
    __syncthreads();
    for (int off = 1; off < NB_MAX; off <<= 1) {
        int x = (t >= off) ? s[t - off] : 0;
        __syncthreads();
        s[t] += x;
        __syncthreads();
    }
    if (t < nb) g_poff[t] = s[t] - v;
}

// local exclusive scan + offset -> rowstart/cursor ; also dinv
__global__ void scanC_kernel(int N) {
    __shared__ int s[256];
    int t = threadIdx.x;
    int n = blockIdx.x * 256 + t;
    int v = (n < N) ? g_deg[n] : 0;
    s[t] = v;
    __syncthreads();
    for (int off = 1; off < 256; off <<= 1) {
        int x = (t >= off) ? s[t - off] : 0;
        __syncthreads();
        s[t] += x;
        __syncthreads();
    }
    if (n < N) {
        int rs = g_poff[blockIdx.x] + s[t] - v;
        g_rowstart[n] = rs;
        g_cursor[n]   = rs;
        g_dinv[n]     = rsqrtf((float)(v + 1));   // +1 self loop
    }
}

__global__ void scatter_kernel(const void* __restrict__ ei, long long E) {
    long long e = blockIdx.x * 256LL + threadIdx.x;
    if (e >= E) return;
    int r, c;
    load_edge(ei, E, e, r, c);
    int pos = atomicAdd(&g_cursor[c], 1);
    g_src[pos] = r;
}

// ---------------- layer-1 dual GEMM:  y = x @ [W1 | Wf1] ----------------
__global__ __launch_bounds__(256, 2) void gemm_kernel(
    const float* __restrict__ x,
    const float* __restrict__ W1, const float* __restrict__ Wf1,
    const float* __restrict__ bf1, int N)
{
    __shared__ float As[2][16][132];
    __shared__ float Bs[2][16][128];

    const int t  = threadIdx.x;
    const int tx = t & 15;
    const int ty = t >> 4;
    const int bm = blockIdx.x * 128;

    float4 aR[2], bR[2];

    auto load_stage = [&](int kc) {
        #pragma unroll
        for (int q = 0; q < 2; q++) {
            int f  = t * 2 + q;
            int m  = f >> 2;
            int k0 = (f & 3) << 2;
            int gm = bm + m;
            aR[q] = (gm < N) ? *(const float4*)(x + (long long)gm * FIN + kc + k0)
                             : make_float4(0.f, 0.f, 0.f, 0.f);
            int n4 = f & 31;
            int kk = f >> 5;
            const float* src = (n4 < 16)
                ? (W1  + (kc + kk) * HH + n4 * 4)
                : (Wf1 + (kc + kk) * HH + (n4 - 16) * 4);
            bR[q] = *(const float4*)src;
        }
    };
    auto store_stage = [&](int bsel) {
        #pragma unroll
        for (int q = 0; q < 2; q++) {
            int f  = t * 2 + q;
            int m  = f >> 2;
            int k0 = (f & 3) << 2;
            As[bsel][k0 + 0][m] = aR[q].x;
            As[bsel][k0 + 1][m] = aR[q].y;
            As[bsel][k0 + 2][m] = aR[q].z;
            As[bsel][k0 + 3][m] = aR[q].w;
            int n4 = f & 31;
            int kk = f >> 5;
            *(float4*)&Bs[bsel][kk][n4 * 4] = bR[q];
        }
    };

    float acc[8][8];
    #pragma unroll
    for (int i = 0; i < 8; i++)
        #pragma unroll
        for (int j = 0; j < 8; j++) acc[i][j] = 0.f;

    load_stage(0);
    store_stage(0);
    __syncthreads();

    int buf = 0;
    #pragma unroll
    for (int s = 0; s < 8; s++) {
        if (s < 7) load_stage((s + 1) * 16);
        #pragma unroll
        for (int kk = 0; kk < 16; kk++) {
            float4 a0  = *(const float4*)&As[buf][kk][ty * 8];
            float4 a1  = *(const float4*)&As[buf][kk][ty * 8 + 4];
            float4 b0  = *(const float4*)&Bs[buf][kk][tx * 8];
            float4 b1v = *(const float4*)&Bs[buf][kk][tx * 8 + 4];
            float av[8] = {a0.x, a0.y, a0.z, a0.w, a1.x, a1.y, a1.z, a1.w};
            float bv[8] = {b0.x, b0.y, b0.z, b0.w, b1v.x, b1v.y, b1v.z, b1v.w};
            #pragma unroll
            for (int i = 0; i < 8; i++)
                #pragma unroll
                for (int j = 0; j < 8; j++)
                    acc[i][j] = fmaf(av[i], bv[j], acc[i][j]);
        }
        if (s < 7) {
            store_stage(buf ^ 1);
            __syncthreads();
            buf ^= 1;
        }
    }

    // epilogue: xs = dinv * y[:, :64] ; xf = y[:, 64:] + bf1
    #pragma unroll
    for (int i = 0; i < 8; i++) {
        int gm = bm + ty * 8 + i;
        if (gm >= N) continue;
        float dv = g_dinv[gm];
        if (tx < 8) {
            #pragma unroll
            for (int j4 = 0; j4 < 2; j4++) {
                float4 v = make_float4(acc[i][j4 * 4] * dv, acc[i][j4 * 4 + 1] * dv,
                                       acc[i][j4 * 4 + 2] * dv, acc[i][j4 * 4 + 3] * dv);
                g_xs[(long long)gm * 16 + tx * 2 + j4] = v;
            }
        } else {
            #pragma unroll
            for (int j4 = 0; j4 < 2; j4++) {
                int c0 = (tx - 8) * 8 + j4 * 4;
                float4 v = make_float4(acc[i][j4 * 4]     + bf1[c0],
                                       acc[i][j4 * 4 + 1] + bf1[c0 + 1],
                                       acc[i][j4 * 4 + 2] + bf1[c0 + 2],
                                       acc[i][j4 * 4 + 3] + bf1[c0 + 3]);
                g_xf[(long long)gm * 16 + (tx - 8) * 2 + j4] = v;
            }
        }
    }
}

// ---------------- fused gather-aggregate + relu + layer-2 dots ----------------
// One warp per node. agg = b1 + dinv_c * (xs_c + sum_in xs_r); then
// h = relu([agg ; xf]); s = h@W2, tt = h@Wf2; u = dinv*s;
// out = b2+bf2+tt + dinv*u (self term of layer-2 GCN).
__global__ __launch_bounds__(256) void aggfin_kernel(
    const float* __restrict__ b1,
    const float* __restrict__ W2,  const float* __restrict__ b2,
    const float* __restrict__ Wf2, const float* __restrict__ bf2,
    float* __restrict__ out, int N)
{
    int gwarp = (blockIdx.x * 256 + threadIdx.x) >> 5;
    int lane  = threadIdx.x & 31;
    if (gwarp >= N) return;

    const float* xsf = (const float*)g_xs;
    const float* xff = (const float*)g_xf;

    // self term
    float acc0 = xsf[(long long)gwarp * 64 + lane];
    float acc1 = xsf[(long long)gwarp * 64 + 32 + lane];

    int rs  = g_rowstart[gwarp];
    int deg = g_deg[gwarp];
    for (int base = 0; base < deg; base += 32) {
        int idx = base + lane;
        int rj = (idx < deg) ? g_src[rs + idx] : 0;
        int cnt = min(32, deg - base);
        for (int k = 0; k < cnt; k++) {
            int r = __shfl_sync(0xFFFFFFFFu, rj, k);
            acc0 += xsf[(long long)r * 64 + lane];
            acc1 += xsf[(long long)r * 64 + 32 + lane];
        }
    }

    float dv = g_dinv[gwarp];
    float a0 = fmaxf(dv * acc0 + b1[lane],      0.f);
    float a1 = fmaxf(dv * acc1 + b1[lane + 32], 0.f);
    float f0 = fmaxf(xff[(long long)gwarp * 64 + lane],      0.f);
    float f1 = fmaxf(xff[(long long)gwarp * 64 + 32 + lane], 0.f);

    float s  = a0 * W2[lane]  + a1 * W2[lane + 32]  + f0 * W2[lane + 64]  + f1 * W2[lane + 96];
    float tt = a0 * Wf2[lane] + a1 * Wf2[lane + 32] + f0 * Wf2[lane + 64] + f1 * Wf2[lane + 96];
    #pragma unroll
    for (int o = 16; o > 0; o >>= 1) {
        s  += __shfl_xor_sync(0xFFFFFFFFu, s, o);
        tt += __shfl_xor_sync(0xFFFFFFFFu, tt, o);
    }
    if (lane == 0) {
        float u = dv * s;
        g_u[gwarp] = u;
        out[gwarp] = b2[0] + bf2[0] + tt + dv * u;
    }
}

// ---------------- layer-2 gather ----------------
__global__ __launch_bounds__(256) void fin2_kernel(float* __restrict__ out, int N) {
    int gwarp = (blockIdx.x * 256 + threadIdx.x) >> 5;
    int lane  = threadIdx.x & 31;
    if (gwarp >= N) return;
    int rs  = g_rowstart[gwarp];
    int deg = g_deg[gwarp];
    float acc = 0.f;
    for (int i = lane; i < deg; i += 32)
        acc += g_u[g_src[rs + i]];
    #pragma unroll
    for (int o = 16; o > 0; o >>= 1)
        acc += __shfl_xor_sync(0xFFFFFFFFu, acc, o);
    if (lane == 0)
        out[gwarp] += g_dinv[gwarp] * acc;
}

// ---------------- launch ----------------
extern "C" void kernel_launch(void* const* d_in, const int* in_sizes, int n_in,
                              void* d_out, int out_size) {
    const float* x   = (const float*)d_in[0];
    const void*  ei  = d_in[1];
    const float* W1  = (const float*)d_in[2];
    const float* b1  = (const float*)d_in[3];
    const float* Wf1 = (const float*)d_in[4];
    const float* bf1 = (const float*)d_in[5];
    const float* W2  = (const float*)d_in[6];
    const float* b2  = (const float*)d_in[7];
    const float* Wf2 = (const float*)d_in[8];
    const float* bf2 = (const float*)d_in[9];
    float* out = (float*)d_out;

    int N = in_sizes[0] / FIN;
    long long E = (long long)in_sizes[1] / 2;
    int nb = (N + 255) / 256;
    int eb = (int)((E + 255) / 256);

    int nwords = (E < 2048) ? (int)E : 2048;
    detect_kernel<<<1, 256>>>((const unsigned long long*)ei, nwords);
    zero_deg_kernel<<<nb, 256>>>(N);
    count_kernel<<<eb, 256>>>(ei, E);
    scanA_kernel<<<nb, 256>>>(N);
    scanB_kernel<<<1, NB_MAX>>>(nb);
    scanC_kernel<<<nb, 256>>>(N);
    scatter_kernel<<<eb, 256>>>(ei, E);
    gemm_kernel<<<(N + 127) / 128, 256>>>(x, W1, Wf1, bf1, N);
    int wb = (int)(((long long)N * 32 + 255) / 256);
    aggfin_kernel<<<wb, 256>>>(b1, W2, b2, Wf2, bf2, out, N);
    fin2_kernel<<<wb, 256>>>(out, N);
}

// round 3
// speedup vs baseline: 1.6929x; 1.4234x over previous
#include <cuda_runtime.h>
#include <cuda_bf16.h>

#define MAXN 100000
#define MAXE 1600000
#define FIN 128
#define HH 64
#define NB_MAX 512

// ---------------- device scratch ----------------
__device__ int    g_is64;
__device__ int    g_deg[MAXN];
__device__ int    g_rowstart[MAXN];
__device__ int    g_cursor[MAXN];
__device__ int    g_src[MAXE];
__device__ int    g_part[NB_MAX];
__device__ int    g_poff[NB_MAX];
__device__ float  g_dinv[MAXN];
__device__ float4 g_xs[MAXN * 16];   // dinv[n] * (x@W1)[n]
__device__ float4 g_xf[MAXN * 16];   // (x@Wf1)[n] + bf1
__device__ float  g_u [MAXN];        // dinv[n] * (h[n]@W2)
// split-bf16 transposed weights: [n(0..127)][k(0..127)]
__device__ __nv_bfloat16 g_Wthi[128 * 128];
__device__ __nv_bfloat16 g_Wtlo[128 * 128];

// ---------------- edge dtype detection ----------------
__global__ void detect_kernel(const unsigned long long* __restrict__ p, int nwords) {
    int bad = 0;
    for (int i = threadIdx.x; i < nwords; i += blockDim.x)
        if (p[i] >= (1ULL << 32)) bad = 1;
    bad = __syncthreads_or(bad);
    if (threadIdx.x == 0) g_is64 = bad ? 0 : 1;
}

__device__ __forceinline__ void load_edge(const void* ei, long long E, long long e,
                                          int& r, int& c) {
    if (g_is64) {
        const long long* p = (const long long*)ei;
        r = (int)p[e]; c = (int)p[E + e];
    } else {
        const int* p = (const int*)ei;
        r = p[e]; c = p[E + e];
    }
}

// ---------------- degree / CSR build ----------------
__global__ void zero_deg_kernel(int N) {
    int n = blockIdx.x * 256 + threadIdx.x;
    if (n < N) g_deg[n] = 0;
}

__global__ void count_kernel(const void* __restrict__ ei, long long E) {
    long long e = blockIdx.x * 256LL + threadIdx.x;
    if (e >= E) return;
    int c;
    if (g_is64) c = (int)((const long long*)ei)[E + e];
    else        c = ((const int*)ei)[E + e];
    atomicAdd(&g_deg[c], 1);
}

__global__ void scanA_kernel(int N) {
    __shared__ int s[8];
    int n = blockIdx.x * 256 + threadIdx.x;
    int v = (n < N) ? g_deg[n] : 0;
    #pragma unroll
    for (int o = 16; o > 0; o >>= 1) v += __shfl_xor_sync(0xFFFFFFFFu, v, o);
    if ((threadIdx.x & 31) == 0) s[threadIdx.x >> 5] = v;
    __syncthreads();
    if (threadIdx.x == 0) {
        int t = 0;
        #pragma unroll
        for (int i = 0; i < 8; i++) t += s[i];
        g_part[blockIdx.x] = t;
    }
}

__global__ void scanB_kernel(int nb) {
    __shared__ int s[NB_MAX];
    int t = threadIdx.x;
    int v = (t < nb) ? g_part[t] : 0;
    s[t] = v;
    __syncthreads();
    for (int off = 1; off < NB_MAX; off <<= 1) {
        int x = (t >= off) ? s[t - off] : 0;
        __syncthreads();
        s[t] += x;
        __syncthreads();
    }
    if (t < nb) g_poff[t] = s[t] - v;
}

__global__ void scanC_kernel(int N) {
    __shared__ int s[256];
    int t = threadIdx.x;
    int n = blockIdx.x * 256 + t;
    int v = (n < N) ? g_deg[n] : 0;
    s[t] = v;
    __syncthreads();
    for (int off = 1; off < 256; off <<= 1) {
        int x = (t >= off) ? s[t - off] : 0;
        __syncthreads();
        s[t] += x;
        __syncthreads();
    }
    if (n < N) {
        int rs = g_poff[blockIdx.x] + s[t] - v;
        g_rowstart[n] = rs;
        g_cursor[n]   = rs;
        g_dinv[n]     = rsqrtf((float)(v + 1));
    }
}

__global__ void scatter_kernel(const void* __restrict__ ei, long long E) {
    long long e = blockIdx.x * 256LL + threadIdx.x;
    if (e >= E) return;
    int r, c;
    load_edge(ei, E, e, r, c);
    int pos = atomicAdd(&g_cursor[c], 1);
    g_src[pos] = r;
}

// ---------------- weight prep: split-bf16 + transpose ----------------
// combined W = [W1 | Wf1] (128 x 128, row k, col n). Store W^T hi/lo.
__global__ void wprep_kernel(const float* __restrict__ W1, const float* __restrict__ Wf1) {
    int idx = blockIdx.x * 256 + threadIdx.x;   // 0..16383
    if (idx >= 128 * 128) return;
    int k = idx >> 7;
    int n = idx & 127;
    float v = (n < HH) ? W1[k * HH + n] : Wf1[k * HH + (n - HH)];
    __nv_bfloat16 hi = __float2bfloat16(v);
    float lo = v - __bfloat162float(hi);
    g_Wthi[n * 128 + k] = hi;
    g_Wtlo[n * 128 + k] = __float2bfloat16(lo);
}

// ---------------- tensor-core dual GEMM (split bf16) ----------------
// CTA: 128 rows x 128 cols, K=128 in 4 tiles of 32. 8 warps as 2(M)x4(N).
// y = x @ [W1|Wf1];  xs = dinv*y[:,:64] ; xf = y[:,64:] + bf1
#define APAD 40   // bf16 elems per SMEM row (80B): g*20 mod 32 covers all bank groups

__device__ __forceinline__ void mma16816(float* c, const unsigned* a, const unsigned* b) {
    asm volatile(
        "mma.sync.aligned.m16n8k16.row.col.f32.bf16.bf16.f32 "
        "{%0,%1,%2,%3}, {%4,%5,%6,%7}, {%8,%9}, {%0,%1,%2,%3};"
        : "+f"(c[0]), "+f"(c[1]), "+f"(c[2]), "+f"(c[3])
        : "r"(a[0]), "r"(a[1]), "r"(a[2]), "r"(a[3]), "r"(b[0]), "r"(b[1]));
}

__global__ __launch_bounds__(256, 2) void gemm_kernel(
    const float* __restrict__ x, const float* __restrict__ bf1, int N)
{
    __shared__ __align__(16) __nv_bfloat16 Ah[128 * APAD];
    __shared__ __align__(16) __nv_bfloat16 Al[128 * APAD];
    __shared__ __align__(16) __nv_bfloat16 Bh[128 * APAD];
    __shared__ __align__(16) __nv_bfloat16 Bl[128 * APAD];

    const int t    = threadIdx.x;
    const int lane = t & 31;
    const int wid  = t >> 5;
    const int g    = lane >> 2;
    const int tg   = lane & 3;
    const int warp_m = wid >> 2;       // 0..1  (64 rows each)
    const int warp_n = wid & 3;        // 0..3  (32 cols each)
    const int bm = blockIdx.x * 128;

    float c[4][4][4];
    #pragma unroll
    for (int mi = 0; mi < 4; mi++)
        #pragma unroll
        for (int ni = 0; ni < 4; ni++)
            #pragma unroll
            for (int q = 0; q < 4; q++) c[mi][ni][q] = 0.f;

    for (int kt = 0; kt < 4; kt++) {
        // ---- load A tile (128 x 32 fp32), split to bf16 hi/lo ----
        #pragma unroll
        for (int i = 0; i < 4; i++) {
            int idx = i * 256 + t;
            int m = idx >> 3;
            int q = idx & 7;
            int gm = bm + m;
            float4 v = (gm < N) ? *(const float4*)(x + (long long)gm * FIN + kt * 32 + q * 4)
                                : make_float4(0.f, 0.f, 0.f, 0.f);
            __nv_bfloat162 h0 = __floats2bfloat162_rn(v.x, v.y);
            __nv_bfloat162 h1 = __floats2bfloat162_rn(v.z, v.w);
            float2 hf0 = __bfloat1622float2(h0);
            float2 hf1 = __bfloat1622float2(h1);
            __nv_bfloat162 l0 = __floats2bfloat162_rn(v.x - hf0.x, v.y - hf0.y);
            __nv_bfloat162 l1 = __floats2bfloat162_rn(v.z - hf1.x, v.w - hf1.y);
            uint2 uh; uh.x = *(unsigned*)&h0; uh.y = *(unsigned*)&h1;
            uint2 ul; ul.x = *(unsigned*)&l0; ul.y = *(unsigned*)&l1;
            *(uint2*)&Ah[m * APAD + q * 4] = uh;
            *(uint2*)&Al[m * APAD + q * 4] = ul;
        }
        // ---- load B tile (128 n x 32 k, pre-split bf16) ----
        #pragma unroll
        for (int i = 0; i < 4; i++) {
            int idx = i * 256 + t;
            int n = idx >> 3;
            int q = idx & 7;
            *(uint2*)&Bh[n * APAD + q * 4] = *(const uint2*)&g_Wthi[n * 128 + kt * 32 + q * 4];
            *(uint2*)&Bl[n * APAD + q * 4] = *(const uint2*)&g_Wtlo[n * 128 + kt * 32 + q * 4];
        }
        __syncthreads();

        #pragma unroll
        for (int kh = 0; kh < 32; kh += 16) {
            unsigned bh[4][2], bl[4][2];
            #pragma unroll
            for (int ni = 0; ni < 4; ni++) {
                int base = (warp_n * 32 + ni * 8 + g) * APAD + kh + 2 * tg;
                bh[ni][0] = *(const unsigned*)&Bh[base];
                bh[ni][1] = *(const unsigned*)&Bh[base + 8];
                bl[ni][0] = *(const unsigned*)&Bl[base];
                bl[ni][1] = *(const unsigned*)&Bl[base + 8];
            }
            #pragma unroll
            for (int mi = 0; mi < 4; mi++) {
                int r0 = (warp_m * 64 + mi * 16 + g) * APAD + kh + 2 * tg;
                int r1 = r0 + 8 * APAD;
                unsigned ah[4], al[4];
                ah[0] = *(const unsigned*)&Ah[r0];
                ah[1] = *(const unsigned*)&Ah[r1];
                ah[2] = *(const unsigned*)&Ah[r0 + 8];
                ah[3] = *(const unsigned*)&Ah[r1 + 8];
                al[0] = *(const unsigned*)&Al[r0];
                al[1] = *(const unsigned*)&Al[r1];
                al[2] = *(const unsigned*)&Al[r0 + 8];
                al[3] = *(const unsigned*)&Al[r1 + 8];
                #pragma unroll
                for (int ni = 0; ni < 4; ni++) {
                    mma16816(c[mi][ni], ah, bh[ni]);
                    mma16816(c[mi][ni], al, bh[ni]);
                    mma16816(c[mi][ni], ah, bl[ni]);
                }
            }
        }
        __syncthreads();
    }

    // ---- epilogue ----
    float* xsf = (float*)g_xs;
    float* xff = (float*)g_xf;
    #pragma unroll
    for (int mi = 0; mi < 4; mi++) {
        int rA = bm + warp_m * 64 + mi * 16 + g;
        int rB = rA + 8;
        float dvA = (rA < N) ? g_dinv[rA] : 0.f;
        float dvB = (rB < N) ? g_dinv[rB] : 0.f;
        #pragma unroll
        for (int ni = 0; ni < 4; ni++) {
            int col = warp_n * 32 + ni * 8 + 2 * tg;
            if (warp_n < 2) {
                if (rA < N)
                    *(float2*)&xsf[(long long)rA * 64 + col] =
                        make_float2(c[mi][ni][0] * dvA, c[mi][ni][1] * dvA);
                if (rB < N)
                    *(float2*)&xsf[(long long)rB * 64 + col] =
                        make_float2(c[mi][ni][2] * dvB, c[mi][ni][3] * dvB);
            } else {
                int cf = col - 64;
                float b0 = bf1[cf], b1v = bf1[cf + 1];
                if (rA < N)
                    *(float2*)&xff[(long long)rA * 64 + cf] =
                        make_float2(c[mi][ni][0] + b0, c[mi][ni][1] + b1v);
                if (rB < N)
                    *(float2*)&xff[(long long)rB * 64 + cf] =
                        make_float2(c[mi][ni][2] + b0, c[mi][ni][3] + b1v);
            }
        }
    }
}

// ---------------- fused gather-aggregate + relu + layer-2 dots ----------------
__global__ __launch_bounds__(256) void aggfin_kernel(
    const float* __restrict__ b1,
    const float* __restrict__ W2,  const float* __restrict__ b2,
    const float* __restrict__ Wf2, const float* __restrict__ bf2,
    float* __restrict__ out, int N)
{
    int gwarp = (blockIdx.x * 256 + threadIdx.x) >> 5;
    int lane  = threadIdx.x & 31;
    if (gwarp >= N) return;

    const float2* xs2 = (const float2*)g_xs;
    const float2* xf2 = (const float2*)g_xf;

    float2 sv = xs2[(long long)gwarp * 32 + lane];   // self term
    float acc0 = sv.x, acc1 = sv.y;

    int rs  = g_rowstart[gwarp];
    int deg = g_deg[gwarp];
    for (int base = 0; base < deg; base += 32) {
        int idx = base + lane;
        int rj = (idx < deg) ? g_src[rs + idx] : 0;
        int cnt = min(32, deg - base);
        for (int k = 0; k < cnt; k++) {
            int r = __shfl_sync(0xFFFFFFFFu, rj, k);
            float2 v = xs2[(long long)r * 32 + lane];
            acc0 += v.x;
            acc1 += v.y;
        }
    }

    float dv = g_dinv[gwarp];
    int c0 = lane * 2;
    float a0 = fmaxf(dv * acc0 + b1[c0],     0.f);
    float a1 = fmaxf(dv * acc1 + b1[c0 + 1], 0.f);
    float2 fv = xf2[(long long)gwarp * 32 + lane];
    float f0 = fmaxf(fv.x, 0.f);
    float f1 = fmaxf(fv.y, 0.f);

    float s  = a0 * W2[c0]  + a1 * W2[c0 + 1]  + f0 * W2[64 + c0]  + f1 * W2[65 + c0];
    float tt = a0 * Wf2[c0] + a1 * Wf2[c0 + 1] + f0 * Wf2[64 + c0] + f1 * Wf2[65 + c0];
    #pragma unroll
    for (int o = 16; o > 0; o >>= 1) {
        s  += __shfl_xor_sync(0xFFFFFFFFu, s, o);
        tt += __shfl_xor_sync(0xFFFFFFFFu, tt, o);
    }
    if (lane == 0) {
        float u = dv * s;
        g_u[gwarp] = u;
        out[gwarp] = b2[0] + bf2[0] + tt + dv * u;
    }
}

// ---------------- layer-2 gather ----------------
__global__ __launch_bounds__(256) void fin2_kernel(float* __restrict__ out, int N) {
    int gwarp = (blockIdx.x * 256 + threadIdx.x) >> 5;
    int lane  = threadIdx.x & 31;
    if (gwarp >= N) return;
    int rs  = g_rowstart[gwarp];
    int deg = g_deg[gwarp];
    float acc = 0.f;
    for (int i = lane; i < deg; i += 32)
        acc += g_u[g_src[rs + i]];
    #pragma unroll
    for (int o = 16; o > 0; o >>= 1)
        acc += __shfl_xor_sync(0xFFFFFFFFu, acc, o);
    if (lane == 0)
        out[gwarp] += g_dinv[gwarp] * acc;
}

// ---------------- launch ----------------
extern "C" void kernel_launch(void* const* d_in, const int* in_sizes, int n_in,
                              void* d_out, int out_size) {
    const float* x   = (const float*)d_in[0];
    const void*  ei  = d_in[1];
    const float* W1  = (const float*)d_in[2];
    const float* b1  = (const float*)d_in[3];
    const float* Wf1 = (const float*)d_in[4];
    const float* bf1 = (const float*)d_in[5];
    const float* W2  = (const float*)d_in[6];
    const float* b2  = (const float*)d_in[7];
    const float* Wf2 = (const float*)d_in[8];
    const float* bf2 = (const float*)d_in[9];
    float* out = (float*)d_out;

    int N = in_sizes[0] / FIN;
    long long E = (long long)in_sizes[1] / 2;
    int nb = (N + 255) / 256;
    int eb = (int)((E + 255) / 256);

    int nwords = (E < 2048) ? (int)E : 2048;
    detect_kernel<<<1, 256>>>((const unsigned long long*)ei, nwords);
    zero_deg_kernel<<<nb, 256>>>(N);
    wprep_kernel<<<64, 256>>>(W1, Wf1);
    count_kernel<<<eb, 256>>>(ei, E);
    scanA_kernel<<<nb, 256>>>(N);
    scanB_kernel<<<1, NB_MAX>>>(nb);
    scanC_kernel<<<nb, 256>>>(N);
    scatter_kernel<<<eb, 256>>>(ei, E);
    gemm_kernel<<<(N + 127) / 128, 256>>>(x, bf1, N);
    int wb = (int)(((long long)N * 32 + 255) / 256);
    aggfin_kernel<<<wb, 256>>>(b1, W2, b2, Wf2, bf2, out, N);
    fin2_kernel<<<wb, 256>>>(out, N);
}

// round 4
// speedup vs baseline: 1.7769x; 1.0496x over previous
#include <cuda_runtime.h>
#include <cuda_bf16.h>

#define MAXN 100000
#define MAXE 1600000
#define FIN 128
#define HH 64
#define NB_MAX 512

// ---------------- device scratch ----------------
__device__ int    g_is64;
__device__ int    g_deg[MAXN];
__device__ int    g_rowstart[MAXN];
__device__ int    g_cursor[MAXN];
__device__ int    g_src[MAXE];
__device__ int    g_part[NB_MAX];
__device__ int    g_poff[NB_MAX];
__device__ float  g_dinv[MAXN];
__device__ float4 g_xs[MAXN * 16];   // dinv[n] * (x@W1)[n]
__device__ float4 g_xf[MAXN * 16];   // (x@Wf1)[n] + bf1
__device__ float  g_u [MAXN];        // dinv[n] * (h[n]@W2)
__device__ __nv_bfloat16 g_Wthi[128 * 128];
__device__ __nv_bfloat16 g_Wtlo[128 * 128];

// ---------------- edge dtype detection ----------------
__global__ void detect_kernel(const unsigned long long* __restrict__ p, int nwords) {
    int bad = 0;
    for (int i = threadIdx.x; i < nwords; i += blockDim.x)
        if (p[i] >= (1ULL << 32)) bad = 1;
    bad = __syncthreads_or(bad);
    if (threadIdx.x == 0) g_is64 = bad ? 0 : 1;
}

__device__ __forceinline__ void load_edge(const void* ei, long long E, long long e,
                                          int& r, int& c) {
    if (g_is64) {
        const long long* p = (const long long*)ei;
        r = (int)p[e]; c = (int)p[E + e];
    } else {
        const int* p = (const int*)ei;
        r = p[e]; c = p[E + e];
    }
}

// ---------------- degree / CSR build ----------------
__global__ void zero_deg_kernel(int N) {
    int n = blockIdx.x * 256 + threadIdx.x;
    if (n < N) g_deg[n] = 0;
}

__global__ void count_kernel(const void* __restrict__ ei, long long E) {
    long long e = blockIdx.x * 256LL + threadIdx.x;
    if (e >= E) return;
    int c;
    if (g_is64) c = (int)((const long long*)ei)[E + e];
    else        c = ((const int*)ei)[E + e];
    atomicAdd(&g_deg[c], 1);
}

__global__ void scanA_kernel(int N) {
    __shared__ int s[8];
    int n = blockIdx.x * 256 + threadIdx.x;
    int v = (n < N) ? g_deg[n] : 0;
    #pragma unroll
    for (int o = 16; o > 0; o >>= 1) v += __shfl_xor_sync(0xFFFFFFFFu, v, o);
    if ((threadIdx.x & 31) == 0) s[threadIdx.x >> 5] = v;
    __syncthreads();
    if (threadIdx.x == 0) {
        int t = 0;
        #pragma unroll
        for (int i = 0; i < 8; i++) t += s[i];
        g_part[blockIdx.x] = t;
    }
}

__global__ void scanB_kernel(int nb) {
    __shared__ int s[NB_MAX];
    int t = threadIdx.x;
    int v = (t < nb) ? g_part[t] : 0;
    s[t] = v;
    __syncthreads();
    for (int off = 1; off < NB_MAX; off <<= 1) {
        int x = (t >= off) ? s[t - off] : 0;
        __syncthreads();
        s[t] += x;
        __syncthreads();
    }
    if (t < nb) g_poff[t] = s[t] - v;
}

__global__ void scanC_kernel(int N) {
    __shared__ int s[256];
    int t = threadIdx.x;
    int n = blockIdx.x * 256 + t;
    int v = (n < N) ? g_deg[n] : 0;
    s[t] = v;
    __syncthreads();
    for (int off = 1; off < 256; off <<= 1) {
        int x = (t >= off) ? s[t - off] : 0;
        __syncthreads();
        s[t] += x;
        __syncthreads();
    }
    if (n < N) {
        int rs = g_poff[blockIdx.x] + s[t] - v;
        g_rowstart[n] = rs;
        g_cursor[n]   = rs;
        g_dinv[n]     = rsqrtf((float)(v + 1));
    }
}

__global__ void scatter_kernel(const void* __restrict__ ei, long long E) {
    long long e = blockIdx.x * 256LL + threadIdx.x;
    if (e >= E) return;
    int r, c;
    load_edge(ei, E, e, r, c);
    int pos = atomicAdd(&g_cursor[c], 1);
    g_src[pos] = r;
}

// ---------------- weight prep: split-bf16 + transpose ----------------
__global__ void wprep_kernel(const float* __restrict__ W1, const float* __restrict__ Wf1) {
    int idx = blockIdx.x * 256 + threadIdx.x;
    if (idx >= 128 * 128) return;
    int k = idx >> 7;
    int n = idx & 127;
    float v = (n < HH) ? W1[k * HH + n] : Wf1[k * HH + (n - HH)];
    __nv_bfloat16 hi = __float2bfloat16(v);
    float lo = v - __bfloat162float(hi);
    g_Wthi[n * 128 + k] = hi;
    g_Wtlo[n * 128 + k] = __float2bfloat16(lo);
}

// ---------------- tensor-core dual GEMM (split bf16) ----------------
#define APAD 40

__device__ __forceinline__ void mma16816(float* c, const unsigned* a, const unsigned* b) {
    asm volatile(
        "mma.sync.aligned.m16n8k16.row.col.f32.bf16.bf16.f32 "
        "{%0,%1,%2,%3}, {%4,%5,%6,%7}, {%8,%9}, {%0,%1,%2,%3};"
        : "+f"(c[0]), "+f"(c[1]), "+f"(c[2]), "+f"(c[3])
        : "r"(a[0]), "r"(a[1]), "r"(a[2]), "r"(a[3]), "r"(b[0]), "r"(b[1]));
}

__global__ __launch_bounds__(256, 2) void gemm_kernel(
    const float* __restrict__ x, const float* __restrict__ bf1, int N)
{
    __shared__ __align__(16) __nv_bfloat16 Ah[128 * APAD];
    __shared__ __align__(16) __nv_bfloat16 Al[128 * APAD];
    __shared__ __align__(16) __nv_bfloat16 Bh[128 * APAD];
    __shared__ __align__(16) __nv_bfloat16 Bl[128 * APAD];

    const int t    = threadIdx.x;
    const int lane = t & 31;
    const int wid  = t >> 5;
    const int g    = lane >> 2;
    const int tg   = lane & 3;
    const int warp_m = wid >> 2;
    const int warp_n = wid & 3;
    const int bm = blockIdx.x * 128;

    float c[4][4][4];
    #pragma unroll
    for (int mi = 0; mi < 4; mi++)
        #pragma unroll
        for (int ni = 0; ni < 4; ni++)
            #pragma unroll
            for (int q = 0; q < 4; q++) c[mi][ni][q] = 0.f;

    for (int kt = 0; kt < 4; kt++) {
        #pragma unroll
        for (int i = 0; i < 4; i++) {
            int idx = i * 256 + t;
            int m = idx >> 3;
            int q = idx & 7;
            int gm = bm + m;
            float4 v = (gm < N) ? *(const float4*)(x + (long long)gm * FIN + kt * 32 + q * 4)
                                : make_float4(0.f, 0.f, 0.f, 0.f);
            __nv_bfloat162 h0 = __floats2bfloat162_rn(v.x, v.y);
            __nv_bfloat162 h1 = __floats2bfloat162_rn(v.z, v.w);
            float2 hf0 = __bfloat1622float2(h0);
            float2 hf1 = __bfloat1622float2(h1);
            __nv_bfloat162 l0 = __floats2bfloat162_rn(v.x - hf0.x, v.y - hf0.y);
            __nv_bfloat162 l1 = __floats2bfloat162_rn(v.z - hf1.x, v.w - hf1.y);
            uint2 uh; uh.x = *(unsigned*)&h0; uh.y = *(unsigned*)&h1;
            uint2 ul; ul.x = *(unsigned*)&l0; ul.y = *(unsigned*)&l1;
            *(uint2*)&Ah[m * APAD + q * 4] = uh;
            *(uint2*)&Al[m * APAD + q * 4] = ul;
        }
        #pragma unroll
        for (int i = 0; i < 4; i++) {
            int idx = i * 256 + t;
            int n = idx >> 3;
            int q = idx & 7;
            *(uint2*)&Bh[n * APAD + q * 4] = *(const uint2*)&g_Wthi[n * 128 + kt * 32 + q * 4];
            *(uint2*)&Bl[n * APAD + q * 4] = *(const uint2*)&g_Wtlo[n * 128 + kt * 32 + q * 4];
        }
        __syncthreads();

        #pragma unroll
        for (int kh = 0; kh < 32; kh += 16) {
            unsigned bh[4][2], bl[4][2];
            #pragma unroll
            for (int ni = 0; ni < 4; ni++) {
                int base = (warp_n * 32 + ni * 8 + g) * APAD + kh + 2 * tg;
                bh[ni][0] = *(const unsigned*)&Bh[base];
                bh[ni][1] = *(const unsigned*)&Bh[base + 8];
                bl[ni][0] = *(const unsigned*)&Bl[base];
                bl[ni][1] = *(const unsigned*)&Bl[base + 8];
            }
            #pragma unroll
            for (int mi = 0; mi < 4; mi++) {
                int r0 = (warp_m * 64 + mi * 16 + g) * APAD + kh + 2 * tg;
                int r1 = r0 + 8 * APAD;
                unsigned ah[4], al[4];
                ah[0] = *(const unsigned*)&Ah[r0];
                ah[1] = *(const unsigned*)&Ah[r1];
                ah[2] = *(const unsigned*)&Ah[r0 + 8];
                ah[3] = *(const unsigned*)&Ah[r1 + 8];
                al[0] = *(const unsigned*)&Al[r0];
                al[1] = *(const unsigned*)&Al[r1];
                al[2] = *(const unsigned*)&Al[r0 + 8];
                al[3] = *(const unsigned*)&Al[r1 + 8];
                #pragma unroll
                for (int ni = 0; ni < 4; ni++) {
                    mma16816(c[mi][ni], ah, bh[ni]);
                    mma16816(c[mi][ni], al, bh[ni]);
                    mma16816(c[mi][ni], ah, bl[ni]);
                }
            }
        }
        __syncthreads();
    }

    float* xsf = (float*)g_xs;
    float* xff = (float*)g_xf;
    #pragma unroll
    for (int mi = 0; mi < 4; mi++) {
        int rA = bm + warp_m * 64 + mi * 16 + g;
        int rB = rA + 8;
        float dvA = (rA < N) ? g_dinv[rA] : 0.f;
        float dvB = (rB < N) ? g_dinv[rB] : 0.f;
        #pragma unroll
        for (int ni = 0; ni < 4; ni++) {
            int col = warp_n * 32 + ni * 8 + 2 * tg;
            if (warp_n < 2) {
                if (rA < N)
                    *(float2*)&xsf[(long long)rA * 64 + col] =
                        make_float2(c[mi][ni][0] * dvA, c[mi][ni][1] * dvA);
                if (rB < N)
                    *(float2*)&xsf[(long long)rB * 64 + col] =
                        make_float2(c[mi][ni][2] * dvB, c[mi][ni][3] * dvB);
            } else {
                int cf = col - 64;
                float b0 = bf1[cf], b1v = bf1[cf + 1];
                if (rA < N)
                    *(float2*)&xff[(long long)rA * 64 + cf] =
                        make_float2(c[mi][ni][0] + b0, c[mi][ni][1] + b1v);
                if (rB < N)
                    *(float2*)&xff[(long long)rB * 64 + cf] =
                        make_float2(c[mi][ni][2] + b0, c[mi][ni][3] + b1v);
            }
        }
    }
}

// ---------------- fused gather-aggregate + relu + layer-2 dots ----------------
// Unrolled x4: 4 independent in-flight gathers per warp (MLP=4).
__global__ __launch_bounds__(256) void aggfin_kernel(
    const float* __restrict__ b1,
    const float* __restrict__ W2,  const float* __restrict__ b2,
    const float* __restrict__ Wf2, const float* __restrict__ bf2,
    float* __restrict__ out, int N)
{
    int gwarp = (blockIdx.x * 256 + threadIdx.x) >> 5;
    int lane  = threadIdx.x & 31;
    if (gwarp >= N) return;

    const float2* xs2 = (const float2*)g_xs;
    const float2* xf2 = (const float2*)g_xf;

    float2 sv = __ldg(&xs2[(long long)gwarp * 32 + lane]);   // self term
    float acc0 = sv.x, acc1 = sv.y;
    float bcc0 = 0.f, bcc1 = 0.f;

    int rs  = g_rowstart[gwarp];
    int deg = g_deg[gwarp];
    for (int base = 0; base < deg; base += 32) {
        int idx = base + lane;
        int rj = (idx < deg) ? g_src[rs + idx] : 0;
        int cnt = min(32, deg - base);
        int k = 0;
        for (; k + 4 <= cnt; k += 4) {
            int r0 = __shfl_sync(0xFFFFFFFFu, rj, k);
            int r1 = __shfl_sync(0xFFFFFFFFu, rj, k + 1);
            int r2 = __shfl_sync(0xFFFFFFFFu, rj, k + 2);
            int r3 = __shfl_sync(0xFFFFFFFFu, rj, k + 3);
            float2 v0 = __ldg(&xs2[(long long)r0 * 32 + lane]);
            float2 v1 = __ldg(&xs2[(long long)r1 * 32 + lane]);
            float2 v2 = __ldg(&xs2[(long long)r2 * 32 + lane]);
            float2 v3 = __ldg(&xs2[(long long)r3 * 32 + lane]);
            acc0 += v0.x; acc1 += v0.y;
            bcc0 += v1.x; bcc1 += v1.y;
            acc0 += v2.x; acc1 += v2.y;
            bcc0 += v3.x; bcc1 += v3.y;
        }
        for (; k < cnt; k++) {
            int r = __shfl_sync(0xFFFFFFFFu, rj, k);
            float2 v = __ldg(&xs2[(long long)r * 32 + lane]);
            acc0 += v.x; acc1 += v.y;
        }
    }
    acc0 += bcc0; acc1 += bcc1;

    float dv = g_dinv[gwarp];
    int c0 = lane * 2;
    float a0 = fmaxf(dv * acc0 + b1[c0],     0.f);
    float a1 = fmaxf(dv * acc1 + b1[c0 + 1], 0.f);
    float2 fv = __ldg(&xf2[(long long)gwarp * 32 + lane]);
    float f0 = fmaxf(fv.x, 0.f);
    float f1 = fmaxf(fv.y, 0.f);

    float s  = a0 * W2[c0]  + a1 * W2[c0 + 1]  + f0 * W2[64 + c0]  + f1 * W2[65 + c0];
    float tt = a0 * Wf2[c0] + a1 * Wf2[c0 + 1] + f0 * Wf2[64 + c0] + f1 * Wf2[65 + c0];
    #pragma unroll
    for (int o = 16; o > 0; o >>= 1) {
        s  += __shfl_xor_sync(0xFFFFFFFFu, s, o);
        tt += __shfl_xor_sync(0xFFFFFFFFu, tt, o);
    }
    if (lane == 0) {
        float u = dv * s;
        g_u[gwarp] = u;
        out[gwarp] = b2[0] + bf2[0] + tt + dv * u;
    }
}

// ---------------- layer-2 gather ----------------
__global__ __launch_bounds__(256) void fin2_kernel(float* __restrict__ out, int N) {
    int gwarp = (blockIdx.x * 256 + threadIdx.x) >> 5;
    int lane  = threadIdx.x & 31;
    if (gwarp >= N) return;
    int rs  = g_rowstart[gwarp];
    int deg = g_deg[gwarp];
    float acc = 0.f;
    for (int i = lane; i < deg; i += 32)
        acc += __ldg(&g_u[g_src[rs + i]]);
    #pragma unroll
    for (int o = 16; o > 0; o >>= 1)
        acc += __shfl_xor_sync(0xFFFFFFFFu, acc, o);
    if (lane == 0)
        out[gwarp] += g_dinv[gwarp] * acc;
}

// ---------------- launch (forked-stream graph) ----------------
extern "C" void kernel_launch(void* const* d_in, const int* in_sizes, int n_in,
                              void* d_out, int out_size) {
    const float* x   = (const float*)d_in[0];
    const void*  ei  = d_in[1];
    const float* W1  = (const float*)d_in[2];
    const float* b1  = (const float*)d_in[3];
    const float* Wf1 = (const float*)d_in[4];
    const float* bf1 = (const float*)d_in[5];
    const float* W2  = (const float*)d_in[6];
    const float* b2  = (const float*)d_in[7];
    const float* Wf2 = (const float*)d_in[8];
    const float* bf2 = (const float*)d_in[9];
    float* out = (float*)d_out;

    int N = in_sizes[0] / FIN;
    long long E = (long long)in_sizes[1] / 2;
    int nb = (N + 255) / 256;
    int eb = (int)((E + 255) / 256);

    // side stream + events, created once on the (uncaptured) correctness call
    static cudaStream_t s1 = nullptr;
    static cudaEvent_t ev0 = nullptr, evW = nullptr, evA = nullptr, evB = nullptr;
    if (!s1) {
        cudaStreamCreateWithFlags(&s1, cudaStreamNonBlocking);
        cudaEventCreateWithFlags(&ev0, cudaEventDisableTiming);
        cudaEventCreateWithFlags(&evW, cudaEventDisableTiming);
        cudaEventCreateWithFlags(&evA, cudaEventDisableTiming);
        cudaEventCreateWithFlags(&evB, cudaEventDisableTiming);
    }
    cudaStream_t s0 = 0;  // capture-origin (legacy default) stream

    int nwords = (E < 2048) ? (int)E : 2048;
    detect_kernel<<<1, 256, 0, s0>>>((const unsigned long long*)ei, nwords);
    cudaEventRecord(ev0, s0);

    // side stream: weight prep (independent of edge work)
    cudaStreamWaitEvent(s1, ev0, 0);
    wprep_kernel<<<64, 256, 0, s1>>>(W1, Wf1);
    cudaEventRecord(evW, s1);

    // main stream: degree + scans
    zero_deg_kernel<<<nb, 256, 0, s0>>>(N);
    count_kernel<<<eb, 256, 0, s0>>>(ei, E);
    scanA_kernel<<<nb, 256, 0, s0>>>(N);
    scanB_kernel<<<1, NB_MAX, 0, s0>>>(nb);
    scanC_kernel<<<nb, 256, 0, s0>>>(N);
    cudaEventRecord(evA, s0);

    // side stream: CSR scatter, overlapped with GEMM
    cudaStreamWaitEvent(s1, evA, 0);
    scatter_kernel<<<eb, 256, 0, s1>>>(ei, E);
    cudaEventRecord(evB, s1);

    // main stream: GEMM (needs dinv from scanC + weights from wprep)
    cudaStreamWaitEvent(s0, evW, 0);
    gemm_kernel<<<(N + 127) / 128, 256, 0, s0>>>(x, bf1, N);

    // join: aggregation needs both GEMM output and CSR
    cudaStreamWaitEvent(s0, evB, 0);
    int wb = (int)(((long long)N * 32 + 255) / 256);
    aggfin_kernel<<<wb, 256, 0, s0>>>(b1, W2, b2, Wf2, bf2, out, N);
    fin2_kernel<<<wb, 256, 0, s0>>>(out, N);
}

// round 5
// speedup vs baseline: 1.7845x; 1.0043x over previous
#include <cuda_runtime.h>
#include <cuda_bf16.h>

#define MAXN 100000
#define MAXE 1600000
#define FIN 128
#define HH 64
#define NB_MAX 512

// ---------------- device scratch ----------------
__device__ int    g_is64;
__device__ int    g_deg[MAXN];
__device__ int    g_rowstart[MAXN];
__device__ int    g_cursor[MAXN];
__device__ int    g_src[MAXE];
__device__ int    g_part[NB_MAX];
__device__ int    g_poff[NB_MAX];
__device__ float  g_dinv[MAXN];
__device__ float4 g_xs[MAXN * 16];   // RAW (x@W1)[n]  (no dinv folded)
__device__ float4 g_xf[MAXN * 16];   // (x@Wf1)[n] + bf1
__device__ float  g_u [MAXN];        // dinv[n] * (h[n]@W2)
__device__ __nv_bfloat16 g_Wthi[128 * 128];
__device__ __nv_bfloat16 g_Wtlo[128 * 128];

// ---------------- edge dtype detection ----------------
__global__ void detect_kernel(const unsigned long long* __restrict__ p, int nwords) {
    int bad = 0;
    for (int i = threadIdx.x; i < nwords; i += blockDim.x)
        if (p[i] >= (1ULL << 32)) bad = 1;
    bad = __syncthreads_or(bad);
    if (threadIdx.x == 0) g_is64 = bad ? 0 : 1;
}

__device__ __forceinline__ void load_edge(const void* ei, long long E, long long e,
                                          int& r, int& c) {
    if (g_is64) {
        const long long* p = (const long long*)ei;
        r = (int)p[e]; c = (int)p[E + e];
    } else {
        const int* p = (const int*)ei;
        r = p[e]; c = p[E + e];
    }
}

// ---------------- degree / CSR build ----------------
__global__ void zero_deg_kernel(int N) {
    int n = blockIdx.x * 256 + threadIdx.x;
    if (n < N) g_deg[n] = 0;
}

__global__ void count_kernel(const void* __restrict__ ei, long long E) {
    long long e = blockIdx.x * 256LL + threadIdx.x;
    if (e >= E) return;
    int c;
    if (g_is64) c = (int)((const long long*)ei)[E + e];
    else        c = ((const int*)ei)[E + e];
    atomicAdd(&g_deg[c], 1);
}

__global__ void scanA_kernel(int N) {
    __shared__ int s[8];
    int n = blockIdx.x * 256 + threadIdx.x;
    int v = (n < N) ? g_deg[n] : 0;
    #pragma unroll
    for (int o = 16; o > 0; o >>= 1) v += __shfl_xor_sync(0xFFFFFFFFu, v, o);
    if ((threadIdx.x & 31) == 0) s[threadIdx.x >> 5] = v;
    __syncthreads();
    if (threadIdx.x == 0) {
        int t = 0;
        #pragma unroll
        for (int i = 0; i < 8; i++) t += s[i];
        g_part[blockIdx.x] = t;
    }
}

__global__ void scanB_kernel(int nb) {
    __shared__ int s[NB_MAX];
    int t = threadIdx.x;
    int v = (t < nb) ? g_part[t] : 0;
    s[t] = v;
    __syncthreads();
    for (int off = 1; off < NB_MAX; off <<= 1) {
        int x = (t >= off) ? s[t - off] : 0;
        __syncthreads();
        s[t] += x;
        __syncthreads();
    }
    if (t < nb) g_poff[t] = s[t] - v;
}

__global__ void scanC_kernel(int N) {
    __shared__ int s[256];
    int t = threadIdx.x;
    int n = blockIdx.x * 256 + t;
    int v = (n < N) ? g_deg[n] : 0;
    s[t] = v;
    __syncthreads();
    for (int off = 1; off < 256; off <<= 1) {
        int x = (t >= off) ? s[t - off] : 0;
        __syncthreads();
        s[t] += x;
        __syncthreads();
    }
    if (n < N) {
        int rs = g_poff[blockIdx.x] + s[t] - v;
        g_rowstart[n] = rs;
        g_cursor[n]   = rs;
        g_dinv[n]     = rsqrtf((float)(v + 1));
    }
}

__global__ void scatter_kernel(const void* __restrict__ ei, long long E) {
    long long e = blockIdx.x * 256LL + threadIdx.x;
    if (e >= E) return;
    int r, c;
    load_edge(ei, E, e, r, c);
    int pos = atomicAdd(&g_cursor[c], 1);
    g_src[pos] = r;
}

// ---------------- weight prep: split-bf16 + transpose ----------------
__global__ void wprep_kernel(const float* __restrict__ W1, const float* __restrict__ Wf1) {
    int idx = blockIdx.x * 256 + threadIdx.x;
    if (idx >= 128 * 128) return;
    int k = idx >> 7;
    int n = idx & 127;
    float v = (n < HH) ? W1[k * HH + n] : Wf1[k * HH + (n - HH)];
    __nv_bfloat16 hi = __float2bfloat16(v);
    float lo = v - __bfloat162float(hi);
    g_Wthi[n * 128 + k] = hi;
    g_Wtlo[n * 128 + k] = __float2bfloat16(lo);
}

// ---------------- tensor-core dual GEMM (split bf16) ----------------
#define APAD 40

__device__ __forceinline__ void mma16816(float* c, const unsigned* a, const unsigned* b) {
    asm volatile(
        "mma.sync.aligned.m16n8k16.row.col.f32.bf16.bf16.f32 "
        "{%0,%1,%2,%3}, {%4,%5,%6,%7}, {%8,%9}, {%0,%1,%2,%3};"
        : "+f"(c[0]), "+f"(c[1]), "+f"(c[2]), "+f"(c[3])
        : "r"(a[0]), "r"(a[1]), "r"(a[2]), "r"(a[3]), "r"(b[0]), "r"(b[1]));
}

__global__ __launch_bounds__(256, 2) void gemm_kernel(
    const float* __restrict__ x, const float* __restrict__ bf1, int N)
{
    __shared__ __align__(16) __nv_bfloat16 Ah[128 * APAD];
    __shared__ __align__(16) __nv_bfloat16 Al[128 * APAD];
    __shared__ __align__(16) __nv_bfloat16 Bh[128 * APAD];
    __shared__ __align__(16) __nv_bfloat16 Bl[128 * APAD];

    const int t    = threadIdx.x;
    const int lane = t & 31;
    const int wid  = t >> 5;
    const int g    = lane >> 2;
    const int tg   = lane & 3;
    const int warp_m = wid >> 2;
    const int warp_n = wid & 3;
    const int bm = blockIdx.x * 128;

    float c[4][4][4];
    #pragma unroll
    for (int mi = 0; mi < 4; mi++)
        #pragma unroll
        for (int ni = 0; ni < 4; ni++)
            #pragma unroll
            for (int q = 0; q < 4; q++) c[mi][ni][q] = 0.f;

    for (int kt = 0; kt < 4; kt++) {
        #pragma unroll
        for (int i = 0; i < 4; i++) {
            int idx = i * 256 + t;
            int m = idx >> 3;
            int q = idx & 7;
            int gm = bm + m;
            float4 v = (gm < N) ? *(const float4*)(x + (long long)gm * FIN + kt * 32 + q * 4)
                                : make_float4(0.f, 0.f, 0.f, 0.f);
            __nv_bfloat162 h0 = __floats2bfloat162_rn(v.x, v.y);
            __nv_bfloat162 h1 = __floats2bfloat162_rn(v.z, v.w);
            float2 hf0 = __bfloat1622float2(h0);
            float2 hf1 = __bfloat1622float2(h1);
            __nv_bfloat162 l0 = __floats2bfloat162_rn(v.x - hf0.x, v.y - hf0.y);
            __nv_bfloat162 l1 = __floats2bfloat162_rn(v.z - hf1.x, v.w - hf1.y);
            uint2 uh; uh.x = *(unsigned*)&h0; uh.y = *(unsigned*)&h1;
            uint2 ul; ul.x = *(unsigned*)&l0; ul.y = *(unsigned*)&l1;
            *(uint2*)&Ah[m * APAD + q * 4] = uh;
            *(uint2*)&Al[m * APAD + q * 4] = ul;
        }
        #pragma unroll
        for (int i = 0; i < 4; i++) {
            int idx = i * 256 + t;
            int n = idx >> 3;
            int q = idx & 7;
            *(uint2*)&Bh[n * APAD + q * 4] = *(const uint2*)&g_Wthi[n * 128 + kt * 32 + q * 4];
            *(uint2*)&Bl[n * APAD + q * 4] = *(const uint2*)&g_Wtlo[n * 128 + kt * 32 + q * 4];
        }
        __syncthreads();

        #pragma unroll
        for (int kh = 0; kh < 32; kh += 16) {
            unsigned bh[4][2], bl[4][2];
            #pragma unroll
            for (int ni = 0; ni < 4; ni++) {
                int base = (warp_n * 32 + ni * 8 + g) * APAD + kh + 2 * tg;
                bh[ni][0] = *(const unsigned*)&Bh[base];
                bh[ni][1] = *(const unsigned*)&Bh[base + 8];
                bl[ni][0] = *(const unsigned*)&Bl[base];
                bl[ni][1] = *(const unsigned*)&Bl[base + 8];
            }
            #pragma unroll
            for (int mi = 0; mi < 4; mi++) {
                int r0 = (warp_m * 64 + mi * 16 + g) * APAD + kh + 2 * tg;
                int r1 = r0 + 8 * APAD;
                unsigned ah[4], al[4];
                ah[0] = *(const unsigned*)&Ah[r0];
                ah[1] = *(const unsigned*)&Ah[r1];
                ah[2] = *(const unsigned*)&Ah[r0 + 8];
                ah[3] = *(const unsigned*)&Ah[r1 + 8];
                al[0] = *(const unsigned*)&Al[r0];
                al[1] = *(const unsigned*)&Al[r1];
                al[2] = *(const unsigned*)&Al[r0 + 8];
                al[3] = *(const unsigned*)&Al[r1 + 8];
                #pragma unroll
                for (int ni = 0; ni < 4; ni++) {
                    mma16816(c[mi][ni], ah, bh[ni]);
                    mma16816(c[mi][ni], al, bh[ni]);
                    mma16816(c[mi][ni], ah, bl[ni]);
                }
            }
        }
        __syncthreads();
    }

    // epilogue: xs = RAW y[:, :64] (no dinv) ; xf = y[:, 64:] + bf1
    float* xsf = (float*)g_xs;
    float* xff = (float*)g_xf;
    #pragma unroll
    for (int mi = 0; mi < 4; mi++) {
        int rA = bm + warp_m * 64 + mi * 16 + g;
        int rB = rA + 8;
        #pragma unroll
        for (int ni = 0; ni < 4; ni++) {
            int col = warp_n * 32 + ni * 8 + 2 * tg;
            if (warp_n < 2) {
                if (rA < N)
                    *(float2*)&xsf[(long long)rA * 64 + col] =
                        make_float2(c[mi][ni][0], c[mi][ni][1]);
                if (rB < N)
                    *(float2*)&xsf[(long long)rB * 64 + col] =
                        make_float2(c[mi][ni][2], c[mi][ni][3]);
            } else {
                int cf = col - 64;
                float b0 = bf1[cf], b1v = bf1[cf + 1];
                if (rA < N)
                    *(float2*)&xff[(long long)rA * 64 + cf] =
                        make_float2(c[mi][ni][0] + b0, c[mi][ni][1] + b1v);
                if (rB < N)
                    *(float2*)&xff[(long long)rB * 64 + cf] =
                        make_float2(c[mi][ni][2] + b0, c[mi][ni][3] + b1v);
            }
        }
    }
}

// ---------------- fused gather-aggregate + relu + layer-2 dots ----------------
// Paired-edge LDG.128 gather: lanes 0-15 even edges, 16-31 odd edges.
// Each lane loads float4 (16 lanes x 16B = full 256B row per edge).
__global__ __launch_bounds__(256) void aggfin_kernel(
    const float* __restrict__ b1,
    const float* __restrict__ W2,  const float* __restrict__ b2,
    const float* __restrict__ Wf2, const float* __restrict__ bf2,
    float* __restrict__ out, int N)
{
    int gwarp = (blockIdx.x * 256 + threadIdx.x) >> 5;
    int lane  = threadIdx.x & 31;
    if (gwarp >= N) return;
    const int half = lane >> 4;
    const int lq   = lane & 15;

    const float4* __restrict__ xs4 = g_xs;
    const float4* __restrict__ xf4 = g_xf;
    const float* __restrict__ dptr = g_dinv;

    float4 accA = make_float4(0.f, 0.f, 0.f, 0.f);
    float4 accB = make_float4(0.f, 0.f, 0.f, 0.f);

    int rs  = g_rowstart[gwarp];
    int deg = g_deg[gwarp];
    for (int base = 0; base < deg; base += 32) {
        int idx = base + lane;
        int rj = (idx < deg) ? g_src[rs + idx] : 0;
        int cnt = min(32, deg - base);
        int k = 0;
        for (; k + 8 <= cnt; k += 8) {
            int s0 = __shfl_sync(0xFFFFFFFFu, rj, k + half);
            int s1 = __shfl_sync(0xFFFFFFFFu, rj, k + 2 + half);
            int s2 = __shfl_sync(0xFFFFFFFFu, rj, k + 4 + half);
            int s3 = __shfl_sync(0xFFFFFFFFu, rj, k + 6 + half);
            float w0 = __ldg(&dptr[s0]);
            float w1 = __ldg(&dptr[s1]);
            float w2 = __ldg(&dptr[s2]);
            float w3 = __ldg(&dptr[s3]);
            float4 v0 = __ldg(&xs4[(long long)s0 * 16 + lq]);
            float4 v1 = __ldg(&xs4[(long long)s1 * 16 + lq]);
            float4 v2 = __ldg(&xs4[(long long)s2 * 16 + lq]);
            float4 v3 = __ldg(&xs4[(long long)s3 * 16 + lq]);
            accA.x = fmaf(w0, v0.x, accA.x); accA.y = fmaf(w0, v0.y, accA.y);
            accA.z = fmaf(w0, v0.z, accA.z); accA.w = fmaf(w0, v0.w, accA.w);
            accB.x = fmaf(w1, v1.x, accB.x); accB.y = fmaf(w1, v1.y, accB.y);
            accB.z = fmaf(w1, v1.z, accB.z); accB.w = fmaf(w1, v1.w, accB.w);
            accA.x = fmaf(w2, v2.x, accA.x); accA.y = fmaf(w2, v2.y, accA.y);
            accA.z = fmaf(w2, v2.z, accA.z); accA.w = fmaf(w2, v2.w, accA.w);
            accB.x = fmaf(w3, v3.x, accB.x); accB.y = fmaf(w3, v3.y, accB.y);
            accB.z = fmaf(w3, v3.z, accB.z); accB.w = fmaf(w3, v3.w, accB.w);
        }
        for (; k + 2 <= cnt; k += 2) {
            int s0 = __shfl_sync(0xFFFFFFFFu, rj, k + half);
            float w = __ldg(&dptr[s0]);
            float4 v = __ldg(&xs4[(long long)s0 * 16 + lq]);
            accA.x = fmaf(w, v.x, accA.x); accA.y = fmaf(w, v.y, accA.y);
            accA.z = fmaf(w, v.z, accA.z); accA.w = fmaf(w, v.w, accA.w);
        }
        if (k < cnt) {   // odd leftover: only half 0 contributes
            int s0 = __shfl_sync(0xFFFFFFFFu, rj, k);
            if (half == 0) {
                float w = __ldg(&dptr[s0]);
                float4 v = __ldg(&xs4[(long long)s0 * 16 + lq]);
                accA.x = fmaf(w, v.x, accA.x); accA.y = fmaf(w, v.y, accA.y);
                accA.z = fmaf(w, v.z, accA.z); accA.w = fmaf(w, v.w, accA.w);
            }
        }
    }
    accA.x += accB.x; accA.y += accB.y; accA.z += accB.z; accA.w += accB.w;
    // combine the two half-warps (lane L gets full sum for chunk L&15)
    accA.x += __shfl_xor_sync(0xFFFFFFFFu, accA.x, 16);
    accA.y += __shfl_xor_sync(0xFFFFFFFFu, accA.y, 16);
    accA.z += __shfl_xor_sync(0xFFFFFFFFu, accA.z, 16);
    accA.w += __shfl_xor_sync(0xFFFFFFFFu, accA.w, 16);

    float dv = dptr[gwarp];
    // self term
    float4 sv = __ldg(&xs4[(long long)gwarp * 16 + lq]);
    accA.x = fmaf(dv, sv.x, accA.x); accA.y = fmaf(dv, sv.y, accA.y);
    accA.z = fmaf(dv, sv.z, accA.z); accA.w = fmaf(dv, sv.w, accA.w);

    int c0 = lq * 4;
    float s, tt;
    if (half == 0) {
        float a0 = fmaxf(dv * accA.x + b1[c0],     0.f);
        float a1 = fmaxf(dv * accA.y + b1[c0 + 1], 0.f);
        float a2 = fmaxf(dv * accA.z + b1[c0 + 2], 0.f);
        float a3 = fmaxf(dv * accA.w + b1[c0 + 3], 0.f);
        s  = a0 * W2[c0]  + a1 * W2[c0 + 1]  + a2 * W2[c0 + 2]  + a3 * W2[c0 + 3];
        tt = a0 * Wf2[c0] + a1 * Wf2[c0 + 1] + a2 * Wf2[c0 + 2] + a3 * Wf2[c0 + 3];
    } else {
        float4 fv = __ldg(&xf4[(long long)gwarp * 16 + lq]);
        float f0 = fmaxf(fv.x, 0.f);
        float f1 = fmaxf(fv.y, 0.f);
        float f2 = fmaxf(fv.z, 0.f);
        float f3 = fmaxf(fv.w, 0.f);
        s  = f0 * W2[64 + c0]  + f1 * W2[65 + c0]  + f2 * W2[66 + c0]  + f3 * W2[67 + c0];
        tt = f0 * Wf2[64 + c0] + f1 * Wf2[65 + c0] + f2 * Wf2[66 + c0] + f3 * Wf2[67 + c0];
    }
    #pragma unroll
    for (int o = 16; o > 0; o >>= 1) {
        s  += __shfl_xor_sync(0xFFFFFFFFu, s, o);
        tt += __shfl_xor_sync(0xFFFFFFFFu, tt, o);
    }
    if (lane == 0) {
        float u = dv * s;
        g_u[gwarp] = u;
        out[gwarp] = b2[0] + bf2[0] + tt + dv * u;
    }
}

// ---------------- layer-2 gather ----------------
__global__ __launch_bounds__(256) void fin2_kernel(float* __restrict__ out, int N) {
    int gwarp = (blockIdx.x * 256 + threadIdx.x) >> 5;
    int lane  = threadIdx.x & 31;
    if (gwarp >= N) return;
    int rs  = g_rowstart[gwarp];
    int deg = g_deg[gwarp];
    float acc = 0.f;
    for (int i = lane; i < deg; i += 32)
        acc += __ldg(&g_u[g_src[rs + i]]);
    #pragma unroll
    for (int o = 16; o > 0; o >>= 1)
        acc += __shfl_xor_sync(0xFFFFFFFFu, acc, o);
    if (lane == 0)
        out[gwarp] += g_dinv[gwarp] * acc;
}

// ---------------- launch (forked-stream graph) ----------------
extern "C" void kernel_launch(void* const* d_in, const int* in_sizes, int n_in,
                              void* d_out, int out_size) {
    const float* x   = (const float*)d_in[0];
    const void*  ei  = d_in[1];
    const float* W1  = (const float*)d_in[2];
    const float* b1  = (const float*)d_in[3];
    const float* Wf1 = (const float*)d_in[4];
    const float* bf1 = (const float*)d_in[5];
    const float* W2  = (const float*)d_in[6];
    const float* b2  = (const float*)d_in[7];
    const float* Wf2 = (const float*)d_in[8];
    const float* bf2 = (const float*)d_in[9];
    float* out = (float*)d_out;

    int N = in_sizes[0] / FIN;
    long long E = (long long)in_sizes[1] / 2;
    int nb = (N + 255) / 256;
    int eb = (int)((E + 255) / 256);

    static cudaStream_t s1 = nullptr;
    static cudaEvent_t ev0 = nullptr, evB = nullptr;
    if (!s1) {
        cudaStreamCreateWithFlags(&s1, cudaStreamNonBlocking);
        cudaEventCreateWithFlags(&ev0, cudaEventDisableTiming);
        cudaEventCreateWithFlags(&evB, cudaEventDisableTiming);
    }
    cudaStream_t s0 = 0;

    int nwords = (E < 2048) ? (int)E : 2048;
    detect_kernel<<<1, 256, 0, s0>>>((const unsigned long long*)ei, nwords);
    cudaEventRecord(ev0, s0);

    // s0: GEMM path (independent of edges now — dinv deferred to aggfin)
    wprep_kernel<<<64, 256, 0, s0>>>(W1, Wf1);
    gemm_kernel<<<(N + 127) / 128, 256, 0, s0>>>(x, bf1, N);

    // s1: full edge pipeline, overlapped with GEMM
    cudaStreamWaitEvent(s1, ev0, 0);
    zero_deg_kernel<<<nb, 256, 0, s1>>>(N);
    count_kernel<<<eb, 256, 0, s1>>>(ei, E);
    scanA_kernel<<<nb, 256, 0, s1>>>(N);
    scanB_kernel<<<1, NB_MAX, 0, s1>>>(nb);
    scanC_kernel<<<nb, 256, 0, s1>>>(N);
    scatter_kernel<<<eb, 256, 0, s1>>>(ei, E);
    cudaEventRecord(evB, s1);

    // join: aggregation needs GEMM output + CSR + dinv
    cudaStreamWaitEvent(s0, evB, 0);
    int wb = (int)(((long long)N * 32 + 255) / 256);
    aggfin_kernel<<<wb, 256, 0, s0>>>(b1, W2, b2, Wf2, bf2, out, N);
    fin2_kernel<<<wb, 256, 0, s0>>>(out, N);
}

// round 6
// speedup vs baseline: 1.8569x; 1.0405x over previous
#include <cuda_runtime.h>
#include <cuda_bf16.h>

#define MAXN 100000
#define MAXE 1600000
#define FIN 128
#define HH 64
#define NB_MAX 512

// ---------------- device scratch ----------------
__device__ int    g_is64;
__device__ int    g_deg[MAXN];
__device__ int    g_rowstart[MAXN];
__device__ int    g_cursor[MAXN];
__device__ int    g_src[MAXE];
__device__ int    g_part[NB_MAX];
__device__ float  g_dinv[MAXN];
__device__ float4 g_xs[MAXN * 16];   // RAW (x@W1)[n]
__device__ float4 g_xf[MAXN * 16];   // (x@Wf1)[n] + bf1
__device__ float  g_u [MAXN];        // dinv[n] * (h[n]@W2)
__device__ __nv_bfloat16 g_Wthi[128 * 128];
__device__ __nv_bfloat16 g_Wtlo[128 * 128];

// ---------------- fused prep: detect + wprep + zero_deg + part init ----------
__global__ void prep_kernel(const unsigned long long* __restrict__ p, int nwords,
                            const float* __restrict__ W1, const float* __restrict__ Wf1,
                            int N) {
    int b = blockIdx.x, t = threadIdx.x;
    if (b == 0) {
        int bad = 0;
        for (int i = t; i < nwords; i += 256)
            if (p[i] >= (1ULL << 32)) bad = 1;
        bad = __syncthreads_or(bad);
        if (t == 0) g_is64 = bad ? 0 : 1;
        g_part[t] = -1;
        g_part[256 + t] = -1;
    } else if (b <= 64) {
        int idx = (b - 1) * 256 + t;          // 0..16383
        int k = idx >> 7;
        int n = idx & 127;
        float v = (n < HH) ? W1[k * HH + n] : Wf1[k * HH + (n - HH)];
        __nv_bfloat16 hi = __float2bfloat16(v);
        float lo = v - __bfloat162float(hi);
        g_Wthi[n * 128 + k] = hi;
        g_Wtlo[n * 128 + k] = __float2bfloat16(lo);
    } else {
        int n = (b - 65) * 256 + t;
        if (n < N) g_deg[n] = 0;
    }
}

// ---------------- count (4 edges/thread, vectorized) ----------------
__global__ void count_kernel(const void* __restrict__ ei, long long E) {
    long long base = (blockIdx.x * 256LL + threadIdx.x) * 4;
    if (base >= E) return;
    if (g_is64) {
        const long long* p = (const long long*)ei + E;   // col array
        if (base + 4 <= E && ((E & 1) == 0)) {
            longlong2 a = *(const longlong2*)&p[base];
            longlong2 b = *(const longlong2*)&p[base + 2];
            atomicAdd(&g_deg[(int)a.x], 1);
            atomicAdd(&g_deg[(int)a.y], 1);
            atomicAdd(&g_deg[(int)b.x], 1);
            atomicAdd(&g_deg[(int)b.y], 1);
        } else {
            for (long long e = base; e < E && e < base + 4; e++)
                atomicAdd(&g_deg[(int)p[e]], 1);
        }
    } else {
        const int* p = (const int*)ei + E;
        if (base + 4 <= E && ((E & 3) == 0)) {
            int4 v = *(const int4*)&p[base];
            atomicAdd(&g_deg[v.x], 1);
            atomicAdd(&g_deg[v.y], 1);
            atomicAdd(&g_deg[v.z], 1);
            atomicAdd(&g_deg[v.w], 1);
        } else {
            for (long long e = base; e < E && e < base + 4; e++)
                atomicAdd(&g_deg[p[e]], 1);
        }
    }
}

// ---------------- single-pass scan (all blocks co-resident) ----------------
// Publishes block total early via atomicExch into -1-initialized g_part, then
// each thread spin-reads predecessor totals (deadlock-free: grid fits on chip
// even while GEMM runs, and GEMM never depends on this kernel).
__global__ __launch_bounds__(256) void scan_kernel(int N) {
    __shared__ int s[256];
    __shared__ int wsum[8];
    __shared__ int prefix;
    int b = blockIdx.x, t = threadIdx.x;
    int n = b * 256 + t;
    int v = (n < N) ? g_deg[n] : 0;

    // fast block total -> publish
    int w = v;
    #pragma unroll
    for (int o = 16; o > 0; o >>= 1) w += __shfl_xor_sync(0xFFFFFFFFu, w, o);
    if ((t & 31) == 0) wsum[t >> 5] = w;
    __syncthreads();
    if (t == 0) {
        int tot = 0;
        #pragma unroll
        for (int i = 0; i < 8; i++) tot += wsum[i];
        atomicExch(&g_part[b], tot);
    }
    __syncthreads();

    // local inclusive scan
    s[t] = v;
    __syncthreads();
    for (int off = 1; off < 256; off <<= 1) {
        int x = (t >= off) ? s[t - off] : 0;
        __syncthreads();
        s[t] += x;
        __syncthreads();
    }

    // lookback: sum predecessor totals (parallel across threads, spin till published)
    int p = 0;
    for (int i = t; i < b; i += 256) {
        int a;
        do { a = atomicAdd(&g_part[i], 0); } while (a < 0);
        p += a;
    }
    #pragma unroll
    for (int o = 16; o > 0; o >>= 1) p += __shfl_xor_sync(0xFFFFFFFFu, p, o);
    if ((t & 31) == 0) wsum[t >> 5] = p;
    __syncthreads();
    if (t == 0) {
        int pr = 0;
        #pragma unroll
        for (int i = 0; i < 8; i++) pr += wsum[i];
        prefix = pr;
    }
    __syncthreads();

    if (n < N) {
        int rs = prefix + s[t] - v;     // exclusive
        g_rowstart[n] = rs;
        g_cursor[n]   = rs;
        g_dinv[n]     = rsqrtf((float)(v + 1));
    }
}

// ---------------- scatter ----------------
__global__ void scatter_kernel(const void* __restrict__ ei, long long E) {
    long long e = blockIdx.x * 256LL + threadIdx.x;
    if (e >= E) return;
    int r, c;
    if (g_is64) {
        const long long* p = (const long long*)ei;
        r = (int)p[e]; c = (int)p[E + e];
    } else {
        const int* p = (const int*)ei;
        r = p[e]; c = p[E + e];
    }
    int pos = atomicAdd(&g_cursor[c], 1);
    g_src[pos] = r;
}

// ---------------- tensor-core dual GEMM (split bf16) ----------------
#define APAD 40

__device__ __forceinline__ void mma16816(float* c, const unsigned* a, const unsigned* b) {
    asm volatile(
        "mma.sync.aligned.m16n8k16.row.col.f32.bf16.bf16.f32 "
        "{%0,%1,%2,%3}, {%4,%5,%6,%7}, {%8,%9}, {%0,%1,%2,%3};"
        : "+f"(c[0]), "+f"(c[1]), "+f"(c[2]), "+f"(c[3])
        : "r"(a[0]), "r"(a[1]), "r"(a[2]), "r"(a[3]), "r"(b[0]), "r"(b[1]));
}

__global__ __launch_bounds__(256, 2) void gemm_kernel(
    const float* __restrict__ x, const float* __restrict__ bf1, int N)
{
    __shared__ __align__(16) __nv_bfloat16 Ah[128 * APAD];
    __shared__ __align__(16) __nv_bfloat16 Al[128 * APAD];
    __shared__ __align__(16) __nv_bfloat16 Bh[128 * APAD];
    __shared__ __align__(16) __nv_bfloat16 Bl[128 * APAD];

    const int t    = threadIdx.x;
    const int lane = t & 31;
    const int wid  = t >> 5;
    const int g    = lane >> 2;
    const int tg   = lane & 3;
    const int warp_m = wid >> 2;
    const int warp_n = wid & 3;
    const int bm = blockIdx.x * 128;

    float c[4][4][4];
    #pragma unroll
    for (int mi = 0; mi < 4; mi++)
        #pragma unroll
        for (int ni = 0; ni < 4; ni++)
            #pragma unroll
            for (int q = 0; q < 4; q++) c[mi][ni][q] = 0.f;

    for (int kt = 0; kt < 4; kt++) {
        #pragma unroll
        for (int i = 0; i < 4; i++) {
            int idx = i * 256 + t;
            int m = idx >> 3;
            int q = idx & 7;
            int gm = bm + m;
            float4 v = (gm < N) ? *(const float4*)(x + (long long)gm * FIN + kt * 32 + q * 4)
                                : make_float4(0.f, 0.f, 0.f, 0.f);
            __nv_bfloat162 h0 = __floats2bfloat162_rn(v.x, v.y);
            __nv_bfloat162 h1 = __floats2bfloat162_rn(v.z, v.w);
            float2 hf0 = __bfloat1622float2(h0);
            float2 hf1 = __bfloat1622float2(h1);
            __nv_bfloat162 l0 = __floats2bfloat162_rn(v.x - hf0.x, v.y - hf0.y);
            __nv_bfloat162 l1 = __floats2bfloat162_rn(v.z - hf1.x, v.w - hf1.y);
            uint2 uh; uh.x = *(unsigned*)&h0; uh.y = *(unsigned*)&h1;
            uint2 ul; ul.x = *(unsigned*)&l0; ul.y = *(unsigned*)&l1;
            *(uint2*)&Ah[m * APAD + q * 4] = uh;
            *(uint2*)&Al[m * APAD + q * 4] = ul;
        }
        #pragma unroll
        for (int i = 0; i < 4; i++) {
            int idx = i * 256 + t;
            int n = idx >> 3;
            int q = idx & 7;
            *(uint2*)&Bh[n * APAD + q * 4] = *(const uint2*)&g_Wthi[n * 128 + kt * 32 + q * 4];
            *(uint2*)&Bl[n * APAD + q * 4] = *(const uint2*)&g_Wtlo[n * 128 + kt * 32 + q * 4];
        }
        __syncthreads();

        #pragma unroll
        for (int kh = 0; kh < 32; kh += 16) {
            unsigned bh[4][2], bl[4][2];
            #pragma unroll
            for (int ni = 0; ni < 4; ni++) {
                int base = (warp_n * 32 + ni * 8 + g) * APAD + kh + 2 * tg;
                bh[ni][0] = *(const unsigned*)&Bh[base];
                bh[ni][1] = *(const unsigned*)&Bh[base + 8];
                bl[ni][0] = *(const unsigned*)&Bl[base];
                bl[ni][1] = *(const unsigned*)&Bl[base + 8];
            }
            #pragma unroll
            for (int mi = 0; mi < 4; mi++) {
                int r0 = (warp_m * 64 + mi * 16 + g) * APAD + kh + 2 * tg;
                int r1 = r0 + 8 * APAD;
                unsigned ah[4], al[4];
                ah[0] = *(const unsigned*)&Ah[r0];
                ah[1] = *(const unsigned*)&Ah[r1];
                ah[2] = *(const unsigned*)&Ah[r0 + 8];
                ah[3] = *(const unsigned*)&Ah[r1 + 8];
                al[0] = *(const unsigned*)&Al[r0];
                al[1] = *(const unsigned*)&Al[r1];
                al[2] = *(const unsigned*)&Al[r0 + 8];
                al[3] = *(const unsigned*)&Al[r1 + 8];
                #pragma unroll
                for (int ni = 0; ni < 4; ni++) {
                    mma16816(c[mi][ni], ah, bh[ni]);
                    mma16816(c[mi][ni], al, bh[ni]);
                    mma16816(c[mi][ni], ah, bl[ni]);
                }
            }
        }
        __syncthreads();
    }

    float* xsf = (float*)g_xs;
    float* xff = (float*)g_xf;
    #pragma unroll
    for (int mi = 0; mi < 4; mi++) {
        int rA = bm + warp_m * 64 + mi * 16 + g;
        int rB = rA + 8;
        #pragma unroll
        for (int ni = 0; ni < 4; ni++) {
            int col = warp_n * 32 + ni * 8 + 2 * tg;
            if (warp_n < 2) {
                if (rA < N)
                    *(float2*)&xsf[(long long)rA * 64 + col] =
                        make_float2(c[mi][ni][0], c[mi][ni][1]);
                if (rB < N)
                    *(float2*)&xsf[(long long)rB * 64 + col] =
                        make_float2(c[mi][ni][2], c[mi][ni][3]);
            } else {
                int cf = col - 64;
                float b0 = bf1[cf], b1v = bf1[cf + 1];
                if (rA < N)
                    *(float2*)&xff[(long long)rA * 64 + cf] =
                        make_float2(c[mi][ni][0] + b0, c[mi][ni][1] + b1v);
                if (rB < N)
                    *(float2*)&xff[(long long)rB * 64 + cf] =
                        make_float2(c[mi][ni][2] + b0, c[mi][ni][3] + b1v);
            }
        }
    }
}

// ---------------- fused gather-aggregate + relu + layer-2 dots ----------------
__global__ __launch_bounds__(256) void aggfin_kernel(
    const float* __restrict__ b1,
    const float* __restrict__ W2,  const float* __restrict__ b2,
    const float* __restrict__ Wf2, const float* __restrict__ bf2,
    float* __restrict__ out, int N)
{
    int gwarp = (blockIdx.x * 256 + threadIdx.x) >> 5;
    int lane  = threadIdx.x & 31;
    if (gwarp >= N) return;
    const int half = lane >> 4;
    const int lq   = lane & 15;

    const float4* __restrict__ xs4 = g_xs;
    const float4* __restrict__ xf4 = g_xf;
    const float* __restrict__ dptr = g_dinv;

    float4 accA = make_float4(0.f, 0.f, 0.f, 0.f);
    float4 accB = make_float4(0.f, 0.f, 0.f, 0.f);

    int rs  = g_rowstart[gwarp];
    int deg = g_deg[gwarp];
    for (int base = 0; base < deg; base += 32) {
        int idx = base + lane;
        int rj = (idx < deg) ? g_src[rs + idx] : 0;
        int cnt = min(32, deg - base);
        int k = 0;
        for (; k + 8 <= cnt; k += 8) {
            int s0 = __shfl_sync(0xFFFFFFFFu, rj, k + half);
            int s1 = __shfl_sync(0xFFFFFFFFu, rj, k + 2 + half);
            int s2 = __shfl_sync(0xFFFFFFFFu, rj, k + 4 + half);
            int s3 = __shfl_sync(0xFFFFFFFFu, rj, k + 6 + half);
            float w0 = __ldg(&dptr[s0]);
            float w1 = __ldg(&dptr[s1]);
            float w2 = __ldg(&dptr[s2]);
            float w3 = __ldg(&dptr[s3]);
            float4 v0 = __ldg(&xs4[(long long)s0 * 16 + lq]);
            float4 v1 = __ldg(&xs4[(long long)s1 * 16 + lq]);
            float4 v2 = __ldg(&xs4[(long long)s2 * 16 + lq]);
            float4 v3 = __ldg(&xs4[(long long)s3 * 16 + lq]);
            accA.x = fmaf(w0, v0.x, accA.x); accA.y = fmaf(w0, v0.y, accA.y);
            accA.z = fmaf(w0, v0.z, accA.z); accA.w = fmaf(w0, v0.w, accA.w);
            accB.x = fmaf(w1, v1.x, accB.x); accB.y = fmaf(w1, v1.y, accB.y);
            accB.z = fmaf(w1, v1.z, accB.z); accB.w = fmaf(w1, v1.w, accB.w);
            accA.x = fmaf(w2, v2.x, accA.x); accA.y = fmaf(w2, v2.y, accA.y);
            accA.z = fmaf(w2, v2.z, accA.z); accA.w = fmaf(w2, v2.w, accA.w);
            accB.x = fmaf(w3, v3.x, accB.x); accB.y = fmaf(w3, v3.y, accB.y);
            accB.z = fmaf(w3, v3.z, accB.z); accB.w = fmaf(w3, v3.w, accB.w);
        }
        for (; k + 2 <= cnt; k += 2) {
            int s0 = __shfl_sync(0xFFFFFFFFu, rj, k + half);
            float w = __ldg(&dptr[s0]);
            float4 v = __ldg(&xs4[(long long)s0 * 16 + lq]);
            accA.x = fmaf(w, v.x, accA.x); accA.y = fmaf(w, v.y, accA.y);
            accA.z = fmaf(w, v.z, accA.z); accA.w = fmaf(w, v.w, accA.w);
        }
        if (k < cnt) {
            int s0 = __shfl_sync(0xFFFFFFFFu, rj, k);
            if (half == 0) {
                float w = __ldg(&dptr[s0]);
                float4 v = __ldg(&xs4[(long long)s0 * 16 + lq]);
                accA.x = fmaf(w, v.x, accA.x); accA.y = fmaf(w, v.y, accA.y);
                accA.z = fmaf(w, v.z, accA.z); accA.w = fmaf(w, v.w, accA.w);
            }
        }
    }
    accA.x += accB.x; accA.y += accB.y; accA.z += accB.z; accA.w += accB.w;
    accA.x += __shfl_xor_sync(0xFFFFFFFFu, accA.x, 16);
    accA.y += __shfl_xor_sync(0xFFFFFFFFu, accA.y, 16);
    accA.z += __shfl_xor_sync(0xFFFFFFFFu, accA.z, 16);
    accA.w += __shfl_xor_sync(0xFFFFFFFFu, accA.w, 16);

    float dv = dptr[gwarp];
    float4 sv = __ldg(&xs4[(long long)gwarp * 16 + lq]);
    accA.x = fmaf(dv, sv.x, accA.x); accA.y = fmaf(dv, sv.y, accA.y);
    accA.z = fmaf(dv, sv.z, accA.z); accA.w = fmaf(dv, sv.w, accA.w);

    int c0 = lq * 4;
    float s, tt;
    if (half == 0) {
        float a0 = fmaxf(dv * accA.x + b1[c0],     0.f);
        float a1 = fmaxf(dv * accA.y + b1[c0 + 1], 0.f);
        float a2 = fmaxf(dv * accA.z + b1[c0 + 2], 0.f);
        float a3 = fmaxf(dv * accA.w + b1[c0 + 3], 0.f);
        s  = a0 * W2[c0]  + a1 * W2[c0 + 1]  + a2 * W2[c0 + 2]  + a3 * W2[c0 + 3];
        tt = a0 * Wf2[c0] + a1 * Wf2[c0 + 1] + a2 * Wf2[c0 + 2] + a3 * Wf2[c0 + 3];
    } else {
        float4 fv = __ldg(&xf4[(long long)gwarp * 16 + lq]);
        float f0 = fmaxf(fv.x, 0.f);
        float f1 = fmaxf(fv.y, 0.f);
        float f2 = fmaxf(fv.z, 0.f);
        float f3 = fmaxf(fv.w, 0.f);
        s  = f0 * W2[64 + c0]  + f1 * W2[65 + c0]  + f2 * W2[66 + c0]  + f3 * W2[67 + c0];
        tt = f0 * Wf2[64 + c0] + f1 * Wf2[65 + c0] + f2 * Wf2[66 + c0] + f3 * Wf2[67 + c0];
    }
    #pragma unroll
    for (int o = 16; o > 0; o >>= 1) {
        s  += __shfl_xor_sync(0xFFFFFFFFu, s, o);
        tt += __shfl_xor_sync(0xFFFFFFFFu, tt, o);
    }
    if (lane == 0) {
        float u = dv * s;
        g_u[gwarp] = u;
        out[gwarp] = b2[0] + bf2[0] + tt + dv * u;
    }
}

// ---------------- layer-2 gather ----------------
__global__ __launch_bounds__(256) void fin2_kernel(float* __restrict__ out, int N) {
    int gwarp = (blockIdx.x * 256 + threadIdx.x) >> 5;
    int lane  = threadIdx.x & 31;
    if (gwarp >= N) return;
    int rs  = g_rowstart[gwarp];
    int deg = g_deg[gwarp];
    float acc = 0.f;
    for (int i = lane; i < deg; i += 32)
        acc += __ldg(&g_u[g_src[rs + i]]);
    #pragma unroll
    for (int o = 16; o > 0; o >>= 1)
        acc += __shfl_xor_sync(0xFFFFFFFFu, acc, o);
    if (lane == 0)
        out[gwarp] += g_dinv[gwarp] * acc;
}

// ---------------- launch (forked-stream graph; aggfin = launch index 5) -------
extern "C" void kernel_launch(void* const* d_in, const int* in_sizes, int n_in,
                              void* d_out, int out_size) {
    const float* x   = (const float*)d_in[0];
    const void*  ei  = d_in[1];
    const float* W1  = (const float*)d_in[2];
    const float* b1  = (const float*)d_in[3];
    const float* Wf1 = (const float*)d_in[4];
    const float* bf1 = (const float*)d_in[5];
    const float* W2  = (const float*)d_in[6];
    const float* b2  = (const float*)d_in[7];
    const float* Wf2 = (const float*)d_in[8];
    const float* bf2 = (const float*)d_in[9];
    float* out = (float*)d_out;

    int N = in_sizes[0] / FIN;
    long long E = (long long)in_sizes[1] / 2;
    int nb = (N + 255) / 256;
    int eb = (int)((E + 255) / 256);
    int eb4 = (int)((E + 1023) / 1024);

    static cudaStream_t s1 = nullptr;
    static cudaEvent_t ev0 = nullptr, evB = nullptr;
    if (!s1) {
        cudaStreamCreateWithFlags(&s1, cudaStreamNonBlocking);
        cudaEventCreateWithFlags(&ev0, cudaEventDisableTiming);
        cudaEventCreateWithFlags(&evB, cudaEventDisableTiming);
    }
    cudaStream_t s0 = 0;

    int nwords = (E < 2048) ? (int)E : 2048;
    // launch 0: prep (detect + wprep + zero_deg + part init)
    prep_kernel<<<65 + nb, 256, 0, s0>>>((const unsigned long long*)ei, nwords, W1, Wf1, N);
    cudaEventRecord(ev0, s0);

    // s1: edge pipeline (launches 1-3)
    cudaStreamWaitEvent(s1, ev0, 0);
    count_kernel<<<eb4, 256, 0, s1>>>(ei, E);
    scan_kernel<<<nb, 256, 0, s1>>>(N);
    scatter_kernel<<<eb, 256, 0, s1>>>(ei, E);
    cudaEventRecord(evB, s1);

    // s0: GEMM (launch 4), overlapped with edge pipeline
    gemm_kernel<<<(N + 127) / 128, 256, 0, s0>>>(x, bf1, N);

    // join (launches 5,6)
    cudaStreamWaitEvent(s0, evB, 0);
    int wb = (int)(((long long)N * 32 + 255) / 256);
    aggfin_kernel<<<wb, 256, 0, s0>>>(b1, W2, b2, Wf2, bf2, out, N);
    fin2_kernel<<<wb, 256, 0, s0>>>(out, N);
}

// round 7
// speedup vs baseline: 1.9327x; 1.0409x over previous
#include <cuda_runtime.h>
#include <cuda_bf16.h>
#include <cuda_fp16.h>

#define MAXN 100000
#define MAXE 1600000
#define FIN 128
#define HH 64
#define NB_MAX 512

// ---------------- device scratch ----------------
__device__ int    g_is64;
__device__ int    g_deg[MAXN];
__device__ int    g_rowstart[MAXN];
__device__ int    g_cursor[MAXN];
__device__ int    g_src[MAXE];
__device__ int    g_part[NB_MAX];
__device__ float  g_dinv[MAXN];
__device__ __half g_xsh[MAXN * 64];  // fp16 RAW (x@W1)[n] — 128B/row, one L2 line
__device__ float4 g_xf[MAXN * 16];   // (x@Wf1)[n] + bf1
__device__ float  g_u [MAXN];        // dinv[n] * (h[n]@W2)
__device__ __nv_bfloat16 g_Wthi[128 * 128];
__device__ __nv_bfloat16 g_Wtlo[128 * 128];

// ---------------- fused prep: detect + wprep + zero_deg + part init ----------
__global__ void prep_kernel(const unsigned long long* __restrict__ p, int nwords,
                            const float* __restrict__ W1, const float* __restrict__ Wf1,
                            int N) {
    int b = blockIdx.x, t = threadIdx.x;
    if (b == 0) {
        int bad = 0;
        for (int i = t; i < nwords; i += 256)
            if (p[i] >= (1ULL << 32)) bad = 1;
        bad = __syncthreads_or(bad);
        if (t == 0) g_is64 = bad ? 0 : 1;
        g_part[t] = -1;
        g_part[256 + t] = -1;
    } else if (b <= 64) {
        int idx = (b - 1) * 256 + t;
        int k = idx >> 7;
        int n = idx & 127;
        float v = (n < HH) ? W1[k * HH + n] : Wf1[k * HH + (n - HH)];
        __nv_bfloat16 hi = __float2bfloat16(v);
        float lo = v - __bfloat162float(hi);
        g_Wthi[n * 128 + k] = hi;
        g_Wtlo[n * 128 + k] = __float2bfloat16(lo);
    } else {
        int n = (b - 65) * 256 + t;
        if (n < N) g_deg[n] = 0;
    }
}

// ---------------- count (4 edges/thread, vectorized) ----------------
__global__ void count_kernel(const void* __restrict__ ei, long long E) {
    long long base = (blockIdx.x * 256LL + threadIdx.x) * 4;
    if (base >= E) return;
    if (g_is64) {
        const long long* p = (const long long*)ei + E;
        if (base + 4 <= E) {
            longlong2 a = *(const longlong2*)&p[base];
            longlong2 b = *(const longlong2*)&p[base + 2];
            atomicAdd(&g_deg[(int)a.x], 1);
            atomicAdd(&g_deg[(int)a.y], 1);
            atomicAdd(&g_deg[(int)b.x], 1);
            atomicAdd(&g_deg[(int)b.y], 1);
        } else {
            for (long long e = base; e < E; e++) atomicAdd(&g_deg[(int)p[e]], 1);
        }
    } else {
        const int* p = (const int*)ei + E;
        if (base + 4 <= E) {
            int4 v = *(const int4*)&p[base];
            atomicAdd(&g_deg[v.x], 1);
            atomicAdd(&g_deg[v.y], 1);
            atomicAdd(&g_deg[v.z], 1);
            atomicAdd(&g_deg[v.w], 1);
        } else {
            for (long long e = base; e < E; e++) atomicAdd(&g_deg[p[e]], 1);
        }
    }
}

// ---------------- single-pass scan ----------------
__global__ __launch_bounds__(256) void scan_kernel(int N) {
    __shared__ int s[256];
    __shared__ int wsum[8];
    __shared__ int prefix;
    int b = blockIdx.x, t = threadIdx.x;
    int n = b * 256 + t;
    int v = (n < N) ? g_deg[n] : 0;

    int w = v;
    #pragma unroll
    for (int o = 16; o > 0; o >>= 1) w += __shfl_xor_sync(0xFFFFFFFFu, w, o);
    if ((t & 31) == 0) wsum[t >> 5] = w;
    __syncthreads();
    if (t == 0) {
        int tot = 0;
        #pragma unroll
        for (int i = 0; i < 8; i++) tot += wsum[i];
        atomicExch(&g_part[b], tot);
    }
    __syncthreads();

    s[t] = v;
    __syncthreads();
    for (int off = 1; off < 256; off <<= 1) {
        int x = (t >= off) ? s[t - off] : 0;
        __syncthreads();
        s[t] += x;
        __syncthreads();
    }

    int p = 0;
    for (int i = t; i < b; i += 256) {
        int a;
        do { a = atomicAdd(&g_part[i], 0); } while (a < 0);
        p += a;
    }
    #pragma unroll
    for (int o = 16; o > 0; o >>= 1) p += __shfl_xor_sync(0xFFFFFFFFu, p, o);
    if ((t & 31) == 0) wsum[t >> 5] = p;
    __syncthreads();
    if (t == 0) {
        int pr = 0;
        #pragma unroll
        for (int i = 0; i < 8; i++) pr += wsum[i];
        prefix = pr;
    }
    __syncthreads();

    if (n < N) {
        int rs = prefix + s[t] - v;
        g_rowstart[n] = rs;
        g_cursor[n]   = rs;
        g_dinv[n]     = rsqrtf((float)(v + 1));
    }
}

// ---------------- scatter (4 edges/thread) ----------------
__global__ void scatter_kernel(const void* __restrict__ ei, long long E) {
    long long base = (blockIdx.x * 256LL + threadIdx.x) * 4;
    if (base >= E) return;
    int r[4], c[4];
    int cnt;
    if (g_is64) {
        const long long* pr = (const long long*)ei;
        const long long* pc = pr + E;
        if (base + 4 <= E) {
            longlong2 r0 = *(const longlong2*)&pr[base];
            longlong2 r1 = *(const longlong2*)&pr[base + 2];
            longlong2 c0 = *(const longlong2*)&pc[base];
            longlong2 c1 = *(const longlong2*)&pc[base + 2];
            r[0] = (int)r0.x; r[1] = (int)r0.y; r[2] = (int)r1.x; r[3] = (int)r1.y;
            c[0] = (int)c0.x; c[1] = (int)c0.y; c[2] = (int)c1.x; c[3] = (int)c1.y;
            cnt = 4;
        } else {
            cnt = (int)(E - base);
            for (int i = 0; i < cnt; i++) { r[i] = (int)pr[base + i]; c[i] = (int)pc[base + i]; }
        }
    } else {
        const int* pr = (const int*)ei;
        const int* pc = pr + E;
        if (base + 4 <= E) {
            int4 rv = *(const int4*)&pr[base];
            int4 cv = *(const int4*)&pc[base];
            r[0] = rv.x; r[1] = rv.y; r[2] = rv.z; r[3] = rv.w;
            c[0] = cv.x; c[1] = cv.y; c[2] = cv.z; c[3] = cv.w;
            cnt = 4;
        } else {
            cnt = (int)(E - base);
            for (int i = 0; i < cnt; i++) { r[i] = pr[base + i]; c[i] = pc[base + i]; }
        }
    }
    #pragma unroll
    for (int i = 0; i < 4; i++) {
        if (i < cnt) {
            int pos = atomicAdd(&g_cursor[c[i]], 1);
            g_src[pos] = r[i];
        }
    }
}

// ---------------- tensor-core dual GEMM (split bf16) ----------------
#define APAD 40

__device__ __forceinline__ void mma16816(float* c, const unsigned* a, const unsigned* b) {
    asm volatile(
        "mma.sync.aligned.m16n8k16.row.col.f32.bf16.bf16.f32 "
        "{%0,%1,%2,%3}, {%4,%5,%6,%7}, {%8,%9}, {%0,%1,%2,%3};"
        : "+f"(c[0]), "+f"(c[1]), "+f"(c[2]), "+f"(c[3])
        : "r"(a[0]), "r"(a[1]), "r"(a[2]), "r"(a[3]), "r"(b[0]), "r"(b[1]));
}

__global__ __launch_bounds__(256, 2) void gemm_kernel(
    const float* __restrict__ x, const float* __restrict__ bf1, int N)
{
    __shared__ __align__(16) __nv_bfloat16 Ah[128 * APAD];
    __shared__ __align__(16) __nv_bfloat16 Al[128 * APAD];
    __shared__ __align__(16) __nv_bfloat16 Bh[128 * APAD];
    __shared__ __align__(16) __nv_bfloat16 Bl[128 * APAD];

    const int t    = threadIdx.x;
    const int lane = t & 31;
    const int wid  = t >> 5;
    const int g    = lane >> 2;
    const int tg   = lane & 3;
    const int warp_m = wid >> 2;
    const int warp_n = wid & 3;
    const int bm = blockIdx.x * 128;

    float c[4][4][4];
    #pragma unroll
    for (int mi = 0; mi < 4; mi++)
        #pragma unroll
        for (int ni = 0; ni < 4; ni++)
            #pragma unroll
            for (int q = 0; q < 4; q++) c[mi][ni][q] = 0.f;

    for (int kt = 0; kt < 4; kt++) {
        #pragma unroll
        for (int i = 0; i < 4; i++) {
            int idx = i * 256 + t;
            int m = idx >> 3;
            int q = idx & 7;
            int gm = bm + m;
            float4 v = (gm < N) ? *(const float4*)(x + (long long)gm * FIN + kt * 32 + q * 4)
                                : make_float4(0.f, 0.f, 0.f, 0.f);
            __nv_bfloat162 h0 = __floats2bfloat162_rn(v.x, v.y);
            __nv_bfloat162 h1 = __floats2bfloat162_rn(v.z, v.w);
            float2 hf0 = __bfloat1622float2(h0);
            float2 hf1 = __bfloat1622float2(h1);
            __nv_bfloat162 l0 = __floats2bfloat162_rn(v.x - hf0.x, v.y - hf0.y);
            __nv_bfloat162 l1 = __floats2bfloat162_rn(v.z - hf1.x, v.w - hf1.y);
            uint2 uh; uh.x = *(unsigned*)&h0; uh.y = *(unsigned*)&h1;
            uint2 ul; ul.x = *(unsigned*)&l0; ul.y = *(unsigned*)&l1;
            *(uint2*)&Ah[m * APAD + q * 4] = uh;
            *(uint2*)&Al[m * APAD + q * 4] = ul;
        }
        #pragma unroll
        for (int i = 0; i < 4; i++) {
            int idx = i * 256 + t;
            int n = idx >> 3;
            int q = idx & 7;
            *(uint2*)&Bh[n * APAD + q * 4] = *(const uint2*)&g_Wthi[n * 128 + kt * 32 + q * 4];
            *(uint2*)&Bl[n * APAD + q * 4] = *(const uint2*)&g_Wtlo[n * 128 + kt * 32 + q * 4];
        }
        __syncthreads();

        #pragma unroll
        for (int kh = 0; kh < 32; kh += 16) {
            unsigned bh[4][2], bl[4][2];
            #pragma unroll
            for (int ni = 0; ni < 4; ni++) {
                int base = (warp_n * 32 + ni * 8 + g) * APAD + kh + 2 * tg;
                bh[ni][0] = *(const unsigned*)&Bh[base];
                bh[ni][1] = *(const unsigned*)&Bh[base + 8];
                bl[ni][0] = *(const unsigned*)&Bl[base];
                bl[ni][1] = *(const unsigned*)&Bl[base + 8];
            }
            #pragma unroll
            for (int mi = 0; mi < 4; mi++) {
                int r0 = (warp_m * 64 + mi * 16 + g) * APAD + kh + 2 * tg;
                int r1 = r0 + 8 * APAD;
                unsigned ah[4], al[4];
                ah[0] = *(const unsigned*)&Ah[r0];
                ah[1] = *(const unsigned*)&Ah[r1];
                ah[2] = *(const unsigned*)&Ah[r0 + 8];
                ah[3] = *(const unsigned*)&Ah[r1 + 8];
                al[0] = *(const unsigned*)&Al[r0];
                al[1] = *(const unsigned*)&Al[r1];
                al[2] = *(const unsigned*)&Al[r0 + 8];
                al[3] = *(const unsigned*)&Al[r1 + 8];
                #pragma unroll
                for (int ni = 0; ni < 4; ni++) {
                    mma16816(c[mi][ni], ah, bh[ni]);
                    mma16816(c[mi][ni], al, bh[ni]);
                    mma16816(c[mi][ni], ah, bl[ni]);
                }
            }
        }
        __syncthreads();
    }

    // epilogue: xs -> fp16 (one 128B line per row) ; xf = y[:, 64:] + bf1 (fp32)
    float* xff = (float*)g_xf;
    #pragma unroll
    for (int mi = 0; mi < 4; mi++) {
        int rA = bm + warp_m * 64 + mi * 16 + g;
        int rB = rA + 8;
        #pragma unroll
        for (int ni = 0; ni < 4; ni++) {
            int col = warp_n * 32 + ni * 8 + 2 * tg;
            if (warp_n < 2) {
                if (rA < N)
                    *(__half2*)&g_xsh[(long long)rA * 64 + col] =
                        __floats2half2_rn(c[mi][ni][0], c[mi][ni][1]);
                if (rB < N)
                    *(__half2*)&g_xsh[(long long)rB * 64 + col] =
                        __floats2half2_rn(c[mi][ni][2], c[mi][ni][3]);
            } else {
                int cf = col - 64;
                float b0 = bf1[cf], b1v = bf1[cf + 1];
                if (rA < N)
                    *(float2*)&xff[(long long)rA * 64 + cf] =
                        make_float2(c[mi][ni][0] + b0, c[mi][ni][1] + b1v);
                if (rB < N)
                    *(float2*)&xff[(long long)rB * 64 + cf] =
                        make_float2(c[mi][ni][2] + b0, c[mi][ni][3] + b1v);
            }
        }
    }
}

// ---------------- fused gather-aggregate + relu + layer-2 dots ----------------
// Paired-edge gather of fp16 rows: lanes 0-15 even edge, 16-31 odd edge.
// Each lane loads uint2 (4 halves); full row = 16 lanes x 8B = 128B = 1 line.
__global__ __launch_bounds__(256) void aggfin_kernel(
    const float* __restrict__ b1,
    const float* __restrict__ W2,  const float* __restrict__ b2,
    const float* __restrict__ Wf2, const float* __restrict__ bf2,
    float* __restrict__ out, int N)
{
    int gwarp = (blockIdx.x * 256 + threadIdx.x) >> 5;
    int lane  = threadIdx.x & 31;
    if (gwarp >= N) return;
    const int half = lane >> 4;
    const int lq   = lane & 15;

    const uint2* __restrict__ xsv = (const uint2*)g_xsh;   // 8 halves.. per uint2 = 4 halves
    const float4* __restrict__ xf4 = g_xf;
    const float* __restrict__ dptr = g_dinv;

    float4 accA = make_float4(0.f, 0.f, 0.f, 0.f);
    float4 accB = make_float4(0.f, 0.f, 0.f, 0.f);

    int rs  = g_rowstart[gwarp];
    int deg = g_deg[gwarp];

    for (int base = 0; base < deg; base += 32) {
        int idx = base + lane;
        int rj = (idx < deg) ? g_src[rs + idx] : 0;
        int cnt = min(32, deg - base);
        int k = 0;
        for (; k + 8 <= cnt; k += 8) {
            int s0 = __shfl_sync(0xFFFFFFFFu, rj, k + half);
            int s1 = __shfl_sync(0xFFFFFFFFu, rj, k + 2 + half);
            int s2 = __shfl_sync(0xFFFFFFFFu, rj, k + 4 + half);
            int s3 = __shfl_sync(0xFFFFFFFFu, rj, k + 6 + half);
            float w0 = __ldg(&dptr[s0]);
            float w1 = __ldg(&dptr[s1]);
            float w2 = __ldg(&dptr[s2]);
            float w3 = __ldg(&dptr[s3]);
            uint2 u0 = __ldg(&xsv[(long long)s0 * 16 + lq]);
            uint2 u1 = __ldg(&xsv[(long long)s1 * 16 + lq]);
            uint2 u2 = __ldg(&xsv[(long long)s2 * 16 + lq]);
            uint2 u3 = __ldg(&xsv[(long long)s3 * 16 + lq]);
            float2 a0 = __half22float2(*(__half2*)&u0.x), a1 = __half22float2(*(__half2*)&u0.y);
            float2 b0 = __half22float2(*(__half2*)&u1.x), b1v = __half22float2(*(__half2*)&u1.y);
            float2 a2 = __half22float2(*(__half2*)&u2.x), a3 = __half22float2(*(__half2*)&u2.y);
            float2 b2v = __half22float2(*(__half2*)&u3.x), b3 = __half22float2(*(__half2*)&u3.y);
            accA.x = fmaf(w0, a0.x, accA.x); accA.y = fmaf(w0, a0.y, accA.y);
            accA.z = fmaf(w0, a1.x, accA.z); accA.w = fmaf(w0, a1.y, accA.w);
            accB.x = fmaf(w1, b0.x, accB.x); accB.y = fmaf(w1, b0.y, accB.y);
            accB.z = fmaf(w1, b1v.x, accB.z); accB.w = fmaf(w1, b1v.y, accB.w);
            accA.x = fmaf(w2, a2.x, accA.x); accA.y = fmaf(w2, a2.y, accA.y);
            accA.z = fmaf(w2, a3.x, accA.z); accA.w = fmaf(w2, a3.y, accA.w);
            accB.x = fmaf(w3, b2v.x, accB.x); accB.y = fmaf(w3, b2v.y, accB.y);
            accB.z = fmaf(w3, b3.x, accB.z); accB.w = fmaf(w3, b3.y, accB.w);
        }
        for (; k + 2 <= cnt; k += 2) {
            int s0 = __shfl_sync(0xFFFFFFFFu, rj, k + half);
            float w = __ldg(&dptr[s0]);
            uint2 u0 = __ldg(&xsv[(long long)s0 * 16 + lq]);
            float2 a0 = __half22float2(*(__half2*)&u0.x), a1 = __half22float2(*(__half2*)&u0.y);
            accA.x = fmaf(w, a0.x, accA.x); accA.y = fmaf(w, a0.y, accA.y);
            accA.z = fmaf(w, a1.x, accA.z); accA.w = fmaf(w, a1.y, accA.w);
        }
        if (k < cnt) {
            int s0 = __shfl_sync(0xFFFFFFFFu, rj, k);
            if (half == 0) {
                float w = __ldg(&dptr[s0]);
                uint2 u0 = __ldg(&xsv[(long long)s0 * 16 + lq]);
                float2 a0 = __half22float2(*(__half2*)&u0.x), a1 = __half22float2(*(__half2*)&u0.y);
                accA.x = fmaf(w, a0.x, accA.x); accA.y = fmaf(w, a0.y, accA.y);
                accA.z = fmaf(w, a1.x, accA.z); accA.w = fmaf(w, a1.y, accA.w);
            }
        }
    }
    accA.x += accB.x; accA.y += accB.y; accA.z += accB.z; accA.w += accB.w;
    accA.x += __shfl_xor_sync(0xFFFFFFFFu, accA.x, 16);
    accA.y += __shfl_xor_sync(0xFFFFFFFFu, accA.y, 16);
    accA.z += __shfl_xor_sync(0xFFFFFFFFu, accA.z, 16);
    accA.w += __shfl_xor_sync(0xFFFFFFFFu, accA.w, 16);

    float dv = dptr[gwarp];
    {   // self term
        uint2 u0 = __ldg(&xsv[(long long)gwarp * 16 + lq]);
        float2 a0 = __half22float2(*(__half2*)&u0.x), a1 = __half22float2(*(__half2*)&u0.y);
        accA.x = fmaf(dv, a0.x, accA.x); accA.y = fmaf(dv, a0.y, accA.y);
        accA.z = fmaf(dv, a1.x, accA.z); accA.w = fmaf(dv, a1.y, accA.w);
    }

    int c0 = lq * 4;
    float s, tt;
    if (half == 0) {
        float a0 = fmaxf(dv * accA.x + b1[c0],     0.f);
        float a1 = fmaxf(dv * accA.y + b1[c0 + 1], 0.f);
        float a2 = fmaxf(dv * accA.z + b1[c0 + 2], 0.f);
        float a3 = fmaxf(dv * accA.w + b1[c0 + 3], 0.f);
        s  = a0 * W2[c0]  + a1 * W2[c0 + 1]  + a2 * W2[c0 + 2]  + a3 * W2[c0 + 3];
        tt = a0 * Wf2[c0] + a1 * Wf2[c0 + 1] + a2 * Wf2[c0 + 2] + a3 * Wf2[c0 + 3];
    } else {
        float4 fv = __ldg(&xf4[(long long)gwarp * 16 + lq]);
        float f0 = fmaxf(fv.x, 0.f);
        float f1 = fmaxf(fv.y, 0.f);
        float f2 = fmaxf(fv.z, 0.f);
        float f3 = fmaxf(fv.w, 0.f);
        s  = f0 * W2[64 + c0]  + f1 * W2[65 + c0]  + f2 * W2[66 + c0]  + f3 * W2[67 + c0];
        tt = f0 * Wf2[64 + c0] + f1 * Wf2[65 + c0] + f2 * Wf2[66 + c0] + f3 * Wf2[67 + c0];
    }
    #pragma unroll
    for (int o = 16; o > 0; o >>= 1) {
        s  += __shfl_xor_sync(0xFFFFFFFFu, s, o);
        tt += __shfl_xor_sync(0xFFFFFFFFu, tt, o);
    }
    if (lane == 0) {
        float u = dv * s;
        g_u[gwarp] = u;
        out[gwarp] = b2[0] + bf2[0] + tt + dv * u;
    }
}

// ---------------- layer-2 gather ----------------
__global__ __launch_bounds__(256) void fin2_kernel(float* __restrict__ out, int N) {
    int gwarp = (blockIdx.x * 256 + threadIdx.x) >> 5;
    int lane  = threadIdx.x & 31;
    if (gwarp >= N) return;
    int rs  = g_rowstart[gwarp];
    int deg = g_deg[gwarp];
    float acc = 0.f;
    for (int i = lane; i < deg; i += 32)
        acc += __ldg(&g_u[g_src[rs + i]]);
    #pragma unroll
    for (int o = 16; o > 0; o >>= 1)
        acc += __shfl_xor_sync(0xFFFFFFFFu, acc, o);
    if (lane == 0)
        out[gwarp] += g_dinv[gwarp] * acc;
}

// ---------------- launch (forked-stream graph) ----------------
extern "C" void kernel_launch(void* const* d_in, const int* in_sizes, int n_in,
                              void* d_out, int out_size) {
    const float* x   = (const float*)d_in[0];
    const void*  ei  = d_in[1];
    const float* W1  = (const float*)d_in[2];
    const float* b1  = (const float*)d_in[3];
    const float* Wf1 = (const float*)d_in[4];
    const float* bf1 = (const float*)d_in[5];
    const float* W2  = (const float*)d_in[6];
    const float* b2  = (const float*)d_in[7];
    const float* Wf2 = (const float*)d_in[8];
    const float* bf2 = (const float*)d_in[9];
    float* out = (float*)d_out;

    int N = in_sizes[0] / FIN;
    long long E = (long long)in_sizes[1] / 2;
    int nb = (N + 255) / 256;
    int eb4 = (int)((E + 1023) / 1024);

    static cudaStream_t s1 = nullptr;
    static cudaEvent_t ev0 = nullptr, evB = nullptr;
    if (!s1) {
        cudaStreamCreateWithFlags(&s1, cudaStreamNonBlocking);
        cudaEventCreateWithFlags(&ev0, cudaEventDisableTiming);
        cudaEventCreateWithFlags(&evB, cudaEventDisableTiming);
    }
    cudaStream_t s0 = 0;

    int nwords = (E < 2048) ? (int)E : 2048;
    prep_kernel<<<65 + nb, 256, 0, s0>>>((const unsigned long long*)ei, nwords, W1, Wf1, N);
    cudaEventRecord(ev0, s0);

    // s1: edge pipeline
    cudaStreamWaitEvent(s1, ev0, 0);
    count_kernel<<<eb4, 256, 0, s1>>>(ei, E);
    scan_kernel<<<nb, 256, 0, s1>>>(N);
    scatter_kernel<<<eb4, 256, 0, s1>>>(ei, E);
    cudaEventRecord(evB, s1);

    // s0: GEMM, overlapped
    gemm_kernel<<<(N + 127) / 128, 256, 0, s0>>>(x, bf1, N);

    // join
    cudaStreamWaitEvent(s0, evB, 0);
    int wb = (int)(((long long)N * 32 + 255) / 256);
    aggfin_kernel<<<wb, 256, 0, s0>>>(b1, W2, b2, Wf2, bf2, out, N);
    fin2_kernel<<<wb, 256, 0, s0>>>(out, N);
}